// round 10
// baseline (speedup 1.0000x reference)
#include <cuda_runtime.h>
#include <cuda_fp16.h>
#include <cstdint>
#include <cstddef>

#define NSEQ  2048
#define CDIM  64
#define CH    512
#define JD    4096
#define BTOT  16
#define ROWS_TOT (BTOT * NSEQ)
#define EPS_F 1e-5f
#define SCALE_F 256.0f          // operand pre-scale (2^8)

// stage (k64): A 128x64 fp16 = 16KB, B 128x64 fp16 = 16KB
#define STAGE_BYTES 32768
#define NSTG 3
#define SMEM_DYN (NSTG * STAGE_BYTES)

// ---------------- scratch ----------------
__device__ __half g_Qt[(size_t)BTOT * CH * NSEQ];    // [b][i][n], x256
__device__ __half g_Kt[(size_t)BTOT * CH * NSEQ];    // [b][j][n], x256
__device__ __half g_V [(size_t)BTOT * NSEQ * CH];    // [b][n][c], x256
__device__ float  g_S [(size_t)BTOT * CH * JD];      // scores, x2^16
__device__ __half g_A [(size_t)BTOT * CH * JD];      // attn fp16 [b][i][j]
__device__ float  g_CTX[(size_t)BTOT * NSEQ * CH];   // true scale
__device__ double g_red[BTOT * 2];

// ---------------- helpers ----------------
__device__ __forceinline__ uint32_t smem_u32(const void* p) {
    uint32_t a;
    asm("{ .reg .u64 t; cvta.to.shared.u64 t, %1; cvt.u32.u64 %0, t; }" : "=r"(a) : "l"(p));
    return a;
}
__device__ __forceinline__ void cp_async16(uint32_t s, const void* g) {
    asm volatile("cp.async.cg.shared.global [%0], [%1], 16;" :: "r"(s), "l"(g) : "memory");
}
__device__ __forceinline__ void cp_commit() {
    asm volatile("cp.async.commit_group;" ::: "memory");
}
template <int N>
__device__ __forceinline__ void cp_wait_group() {
    asm volatile("cp.async.wait_group %0;" :: "n"(N) : "memory");
}
// SW128 swizzle for 128-byte rows
__device__ __forceinline__ uint32_t swz(uint32_t off) {
    return off ^ ((off >> 3) & 0x70);
}
__device__ __forceinline__ void mma16816h(float* c, const uint32_t a[4],
                                          uint32_t b0, uint32_t b1) {
    asm volatile(
        "mma.sync.aligned.m16n8k16.row.col.f32.f16.f16.f32 "
        "{%0,%1,%2,%3}, {%4,%5,%6,%7}, {%8,%9}, {%0,%1,%2,%3};"
        : "+f"(c[0]), "+f"(c[1]), "+f"(c[2]), "+f"(c[3])
        : "r"(a[0]), "r"(a[1]), "r"(a[2]), "r"(a[3]), "r"(b0), "r"(b1));
}
__device__ __forceinline__ void ldsm4(uint32_t r[4], uint32_t addr) {
    asm volatile("ldmatrix.sync.aligned.m8n8.x4.shared.b16 {%0,%1,%2,%3}, [%4];"
                 : "=r"(r[0]), "=r"(r[1]), "=r"(r[2]), "=r"(r[3]) : "r"(addr));
}

// load 128 x 64 fp16 tile (128B rows) into SW128-swizzled smem (256 threads)
__device__ __forceinline__ void ldtile(uint32_t sdst, const char* g, size_t stride, int tid) {
#pragma unroll
    for (int t = 0; t < 4; t++) {
        int op = tid + t * 256;
        int row = op >> 3, c = op & 7;
        uint32_t off = row * 128 + c * 16;
        cp_async16(sdst + swz(off), g + (size_t)row * stride + c * 16);
    }
}

// ============================================================================
// single-term fp16 compute for one k64 stage; warp tile 64x32 (4 mt x 4 nt)
// Register double-buffered fragments: prefetch k16 group kk+1 while issuing
// kk's MMAs. baseA/baseB pre-swizzled; k-offset via XOR (row bits 5-6 zero).
// ============================================================================
__device__ __forceinline__ void compute_stage(uint32_t sA, uint32_t sB,
                                              const uint32_t baseA[4],
                                              const uint32_t baseB[2],
                                              float acc[4][4][4]) {
    uint32_t ah[2][4][4], bf[2][2][4];
#pragma unroll
    for (int mt = 0; mt < 4; mt++) ldsm4(ah[0][mt], sA + baseA[mt]);
#pragma unroll
    for (int np = 0; np < 2; np++) ldsm4(bf[0][np], sB + baseB[np]);

#pragma unroll
    for (int kk = 0; kk < 4; kk++) {
        int cur = kk & 1, nxt = cur ^ 1;
        if (kk < 3) {
            uint32_t kb = (kk + 1) * 32;
#pragma unroll
            for (int mt = 0; mt < 4; mt++) ldsm4(ah[nxt][mt], sA + (baseA[mt] ^ kb));
#pragma unroll
            for (int np = 0; np < 2; np++) ldsm4(bf[nxt][np], sB + (baseB[np] ^ kb));
        }
#pragma unroll
        for (int np = 0; np < 2; np++) {
#pragma unroll
            for (int h = 0; h < 2; h++) {
                uint32_t b0 = bf[cur][np][h], b1 = bf[cur][np][2 + h];
                int nt = np * 2 + h;
#pragma unroll
                for (int mt = 0; mt < 4; mt++)
                    mma16816h(acc[mt][nt], ah[cur][mt], b0, b1);
            }
        }
    }
}

// ============================================================================
// scores: S[ob][i][j] = sum_n Qt[ob][i][n] * Kt[kvb][jc][n]   (x 2^16)
// CTA tile 128(i) x 128(j), grid (32, 4, 16), block 256, 2 CTAs/SM
// smem-staged coalesced epilogue + fused per-batch sum/sumsq.
// ============================================================================
__global__ void __launch_bounds__(256, 2) scores_mma() {
    extern __shared__ char dsm[];
    uint32_t sb = smem_u32(dsm);
    __shared__ double sred[8], sred2[8];

    int ob = blockIdx.z;
    int kvbase = (ob < 8) ? 8 : 0;
    int i0 = blockIdx.y << 7;
    int j0 = blockIdx.x << 7;
    int kvb = kvbase + (j0 >> 9);
    int jc0 = j0 & 511;

    int tid = threadIdx.x;
    int wid = tid >> 5, lane = tid & 31;
    int g = lane >> 2, tg = lane & 3;
    int wm = (wid & 1) * 64, wn = (wid >> 1) * 32;

    uint32_t baseA[4], baseB[2];
    uint32_t lrow = lane & 15, lcol = (lane >> 4) * 16;
#pragma unroll
    for (int mt = 0; mt < 4; mt++) baseA[mt] = swz((wm + mt * 16 + lrow) * 128 + lcol);
#pragma unroll
    for (int np = 0; np < 2; np++) baseB[np] = swz((wn + np * 16 + lrow) * 128 + lcol);

    const char* AB = (const char*)g_Qt + ((size_t)ob * CH + i0) * NSEQ * 2;
    const char* BB = (const char*)g_Kt + ((size_t)kvb * CH + jc0) * NSEQ * 2;
    const size_t st = NSEQ * 2;

    float acc[4][4][4];
#pragma unroll
    for (int a = 0; a < 4; a++)
#pragma unroll
        for (int b = 0; b < 4; b++)
#pragma unroll
            for (int c = 0; c < 4; c++) acc[a][b][c] = 0.f;

    const int NCH = NSEQ / 64;   // 32

    auto load_chunk = [&](int c, int stg) {
        uint32_t s = sb + stg * STAGE_BYTES;
        size_t ko = (size_t)c * 128;
        ldtile(s,         AB + ko, st, tid);
        ldtile(s + 16384, BB + ko, st, tid);
        cp_commit();
    };

    load_chunk(0, 0);
    load_chunk(1, 1);
    for (int c = 0; c < NCH; c++) {
        if (c + 1 < NCH) cp_wait_group<1>(); else cp_wait_group<0>();
        __syncthreads();
        if (c + 2 < NCH) load_chunk(c + 2, (c + 2) % NSTG);
        uint32_t s = sb + (c % NSTG) * STAGE_BYTES;
        compute_stage(s, s + 16384, baseA, baseB, acc);
    }

    // epilogue: stage tile in smem, then coalesced float4 writes + sum/sumsq
    __syncthreads();
    float* stage = (float*)dsm;   // [128][132]
#pragma unroll
    for (int mt = 0; mt < 4; mt++) {
#pragma unroll
        for (int nt = 0; nt < 4; nt++) {
            int row = wm + mt * 16 + g;
            int col = wn + nt * 8 + tg * 2;
            *(float2*)&stage[row * 132 + col] =
                make_float2(acc[mt][nt][0], acc[mt][nt][1]);
            *(float2*)&stage[(row + 8) * 132 + col] =
                make_float2(acc[mt][nt][2], acc[mt][nt][3]);
        }
    }
    __syncthreads();

    float* gout = g_S + (size_t)ob * CH * JD;
    float s1 = 0.f, s2 = 0.f;
#pragma unroll
    for (int k = 0; k < 16; k++) {
        int idx = tid + k * 256;
        int row = idx >> 5, c4 = (idx & 31) * 4;
        float4 v = *(float4*)&stage[row * 132 + c4];
        *(float4*)&gout[(size_t)(i0 + row) * JD + j0 + c4] = v;
        s1 += v.x + v.y + v.z + v.w;
        s2 += v.x * v.x + v.y * v.y + v.z * v.z + v.w * v.w;
    }
    double d1 = (double)s1, d2 = (double)s2;
    for (int off = 16; off > 0; off >>= 1) {
        d1 += __shfl_down_sync(0xffffffffu, d1, off);
        d2 += __shfl_down_sync(0xffffffffu, d2, off);
    }
    if (lane == 0) { sred[wid] = d1; sred2[wid] = d2; }
    __syncthreads();
    if (tid == 0) {
        double t1 = 0.0, t2 = 0.0;
#pragma unroll
        for (int w = 0; w < 8; w++) { t1 += sred[w]; t2 += sred2[w]; }
        atomicAdd(&g_red[2 * ob], t1);
        atomicAdd(&g_red[2 * ob + 1], t2);
    }
}

// ============================================================================
// ctx: CTX[ob][n][i] = sum_j V[kvb(j)][n][jc] * attn[ob][i][j]
// CTA tile 128(n) x 128(i), grid (4, 16, 16), block 256, 2 CTAs/SM
// ============================================================================
__global__ void __launch_bounds__(256, 2) ctx_mma() {
    extern __shared__ char dsm[];
    uint32_t sb = smem_u32(dsm);

    int ob = blockIdx.z;
    int kvbase = (ob < 8) ? 8 : 0;
    int i0 = blockIdx.x << 7;
    int n0 = blockIdx.y << 7;

    int tid = threadIdx.x;
    int wid = tid >> 5, lane = tid & 31;
    int g = lane >> 2, tg = lane & 3;
    int wm = (wid & 1) * 64, wn = (wid >> 1) * 32;

    uint32_t baseA[4], baseB[2];
    uint32_t lrow = lane & 15, lcol = (lane >> 4) * 16;
#pragma unroll
    for (int mt = 0; mt < 4; mt++) baseA[mt] = swz((wm + mt * 16 + lrow) * 128 + lcol);
#pragma unroll
    for (int np = 0; np < 2; np++) baseB[np] = swz((wn + np * 16 + lrow) * 128 + lcol);

    const char* BB = (const char*)g_A + ((size_t)ob * CH + i0) * JD * 2;

    float acc[4][4][4];
#pragma unroll
    for (int a = 0; a < 4; a++)
#pragma unroll
        for (int b = 0; b < 4; b++)
#pragma unroll
            for (int c = 0; c < 4; c++) acc[a][b][c] = 0.f;

    const int NCH = JD / 64;   // 64

    auto load_chunk = [&](int c, int stg) {
        uint32_t s = sb + stg * STAGE_BYTES;
        int j0c = c * 64;
        int kvb = kvbase + (j0c >> 9);
        int jc0 = j0c & 511;
        const char* Ap = (const char*)g_V + (((size_t)kvb * NSEQ + n0) * CH + jc0) * 2;
        ldtile(s,         Ap, CH * 2, tid);
        ldtile(s + 16384, BB + (size_t)j0c * 2, JD * 2, tid);
        cp_commit();
    };

    load_chunk(0, 0);
    load_chunk(1, 1);
    for (int c = 0; c < NCH; c++) {
        if (c + 1 < NCH) cp_wait_group<1>(); else cp_wait_group<0>();
        __syncthreads();
        if (c + 2 < NCH) load_chunk(c + 2, (c + 2) % NSTG);
        uint32_t s = sb + (c % NSTG) * STAGE_BYTES;
        compute_stage(s, s + 16384, baseA, baseB, acc);
    }

    const float ds = 1.0f / SCALE_F;   // undo V pre-scale
    float* gout = g_CTX + (size_t)ob * NSEQ * CH;
#pragma unroll
    for (int mt = 0; mt < 4; mt++) {
#pragma unroll
        for (int nt = 0; nt < 4; nt++) {
            int row = n0 + wm + mt * 16 + g;
            int col = i0 + wn + nt * 8 + tg * 2;
            *(float2*)&gout[(size_t)row * CH + col] =
                make_float2(acc[mt][nt][0] * ds, acc[mt][nt][1] * ds);
            *(float2*)&gout[(size_t)(row + 8) * CH + col] =
                make_float2(acc[mt][nt][2] * ds, acc[mt][nt][3] * ds);
        }
    }
}

// ============================================================================
// fused QKV projection: Qt/Kt (transposed) + V (row) from one emb tile read.
// grid (CH/64=8, ROWS_TOT/64=512), 256 threads. Also zeroes g_red.
// ============================================================================
__global__ void __launch_bounds__(256) qkv_gemm(const float* __restrict__ A,
                                                const float* __restrict__ BmQ,
                                                const float* __restrict__ BmK,
                                                const float* __restrict__ BmV,
                                                __half* __restrict__ Qt,
                                                __half* __restrict__ Kt,
                                                __half* __restrict__ Vv) {
    __shared__ __align__(16) float As[16][68];
    __shared__ __align__(16) float BsQ[16][64], BsK[16][64], BsV[16][64];
    const int K = CDIM, N = CH;
    int bm = blockIdx.y * 64, bn = blockIdx.x * 64;
    int tid = threadIdx.x;

    if (blockIdx.x == 0 && blockIdx.y == 0 && tid < BTOT * 2)
        g_red[tid] = 0.0;

    int tx = tid & 15, ty = tid >> 4;
    int am = tid >> 2, ak = (tid & 3) << 2;
    int br = tid >> 4, bc = (tid & 15) << 2;
    const float* Aptr = A + (size_t)(bm + am) * K + ak;

    float aq[4][4], akk[4][4], av_[4][4];
#pragma unroll
    for (int i = 0; i < 4; i++)
#pragma unroll
        for (int j = 0; j < 4; j++) { aq[i][j] = 0.f; akk[i][j] = 0.f; av_[i][j] = 0.f; }

    for (int k0 = 0; k0 < K; k0 += 16) {
        float4 avv = *(const float4*)(Aptr + k0);
        As[ak + 0][am] = avv.x; As[ak + 1][am] = avv.y;
        As[ak + 2][am] = avv.z; As[ak + 3][am] = avv.w;
        size_t boff = (size_t)(k0 + br) * N + bn + bc;
        *(float4*)&BsQ[br][bc] = *(const float4*)&BmQ[boff];
        *(float4*)&BsK[br][bc] = *(const float4*)&BmK[boff];
        *(float4*)&BsV[br][bc] = *(const float4*)&BmV[boff];
        __syncthreads();
#pragma unroll
        for (int kk = 0; kk < 16; kk++) {
            float a0 = As[kk][ty * 4 + 0], a1 = As[kk][ty * 4 + 1];
            float a2 = As[kk][ty * 4 + 2], a3 = As[kk][ty * 4 + 3];
#pragma unroll
            for (int j = 0; j < 4; j++) {
                float bq = BsQ[kk][tx * 4 + j];
                float bk = BsK[kk][tx * 4 + j];
                float bv = BsV[kk][tx * 4 + j];
                aq[0][j] += a0 * bq; aq[1][j] += a1 * bq; aq[2][j] += a2 * bq; aq[3][j] += a3 * bq;
                akk[0][j] += a0 * bk; akk[1][j] += a1 * bk; akk[2][j] += a2 * bk; akk[3][j] += a3 * bk;
                av_[0][j] += a0 * bv; av_[1][j] += a1 * bv; av_[2][j] += a2 * bv; av_[3][j] += a3 * bv;
            }
        }
        __syncthreads();
    }

    // Qt / Kt transposed epilogue: out[b][col][n]
    {
        int b = bm >> 11;
        int nloc = (bm & 2047) + ty * 4;
#pragma unroll
        for (int j = 0; j < 4; j++) {
            int col = bn + tx * 4 + j;
            union { __half v[4]; uint2 u; } pq, pk;
#pragma unroll
            for (int i = 0; i < 4; i++) {
                pq.v[i] = __float2half(aq[i][j] * SCALE_F);
                pk.v[i] = __float2half(akk[i][j] * SCALE_F);
            }
            size_t off = (size_t)b * (CH * NSEQ) + (size_t)col * NSEQ + nloc;
            *(uint2*)&Qt[off] = pq.u;
            *(uint2*)&Kt[off] = pk.u;
        }
    }
    // V row-major epilogue
#pragma unroll
    for (int i = 0; i < 4; i++) {
        int m = bm + ty * 4 + i;
        union { __half v[4]; uint2 u; } pv;
#pragma unroll
        for (int j = 0; j < 4; j++)
            pv.v[j] = __float2half(av_[i][j] * SCALE_F);
        *(uint2*)&Vv[(size_t)m * CH + bn + tx * 4] = pv.u;
    }
}

// ============================================================================
// out projection fp32: C[M,64] = CTX[M,512] @ Wo[512,64]; 128x64 tile.
// ============================================================================
__global__ void __launch_bounds__(256) gemm_out(const float* __restrict__ A,
                                                const float* __restrict__ Bm,
                                                float* __restrict__ Cm) {
    __shared__ __align__(16) float As[16][132];
    __shared__ __align__(16) float Bs[16][64];
    const int K = CH, N = CDIM;
    int bm = blockIdx.x * 128;
    int tid = threadIdx.x;
    int tx = tid & 15, ty = tid >> 4;
    int am = tid >> 2, ak = (tid & 3) << 2;
    int br = tid >> 4, bc = (tid & 15) << 2;

    float acc[8][4];
#pragma unroll
    for (int i = 0; i < 8; i++)
#pragma unroll
        for (int j = 0; j < 4; j++) acc[i][j] = 0.f;

    for (int k0 = 0; k0 < K; k0 += 16) {
        float4 a0v = *(const float4*)&A[(size_t)(bm + am) * K + k0 + ak];
        float4 a1v = *(const float4*)&A[(size_t)(bm + am + 64) * K + k0 + ak];
        As[ak + 0][am] = a0v.x; As[ak + 1][am] = a0v.y;
        As[ak + 2][am] = a0v.z; As[ak + 3][am] = a0v.w;
        As[ak + 0][am + 64] = a1v.x; As[ak + 1][am + 64] = a1v.y;
        As[ak + 2][am + 64] = a1v.z; As[ak + 3][am + 64] = a1v.w;
        *(float4*)&Bs[br][bc] = *(const float4*)&Bm[(size_t)(k0 + br) * N + bc];
        __syncthreads();
#pragma unroll
        for (int kk = 0; kk < 16; kk++) {
            float a[8], b[4];
            *(float4*)&a[0] = *(float4*)&As[kk][ty * 8];
            *(float4*)&a[4] = *(float4*)&As[kk][ty * 8 + 4];
            *(float4*)&b[0] = *(float4*)&Bs[kk][tx * 4];
#pragma unroll
            for (int i = 0; i < 8; i++)
#pragma unroll
                for (int j = 0; j < 4; j++) acc[i][j] += a[i] * b[j];
        }
        __syncthreads();
    }
#pragma unroll
    for (int i = 0; i < 8; i++) {
        float4 v = make_float4(acc[i][0], acc[i][1], acc[i][2], acc[i][3]);
        *(float4*)&Cm[(size_t)(bm + ty * 8 + i) * N + tx * 4] = v;
    }
}

// ============================================================================
// softmax (fused rstd finalize): scale + softmax over j, write attn fp16.
// ============================================================================
__global__ void __launch_bounds__(256) softmax_k() {
    int row = blockIdx.x;
    int b = row >> 9;
    __shared__ float srstd;
    __shared__ float red[8];
    int t = threadIdx.x;

    if (t == 0) {
        const double SC = 65536.0;   // scores are scaled by 2^16
        double n = (double)CH * (double)JD;
        double mean = g_red[2 * b] / (n * SC);
        double var  = g_red[2 * b + 1] / (n * SC * SC) - mean * mean;
        srstd = rsqrtf((float)var + EPS_F) / (float)SC;
    }

    const float* p = g_S + (size_t)row * JD;
    float4 xv[4];
#pragma unroll
    for (int u = 0; u < 4; u++)
        xv[u] = *(const float4*)&p[u * 1024 + t * 4];
    __syncthreads();
    float rstd = srstd;

    float* x = (float*)xv;
    float mx = -1e30f;
#pragma unroll
    for (int u = 0; u < 16; u++) {
        x[u] *= rstd;
        mx = fmaxf(mx, x[u]);
    }
    for (int off = 16; off > 0; off >>= 1)
        mx = fmaxf(mx, __shfl_xor_sync(0xffffffffu, mx, off));
    int lane = t & 31, wid = t >> 5;
    if (lane == 0) red[wid] = mx;
    __syncthreads();
    float gm = red[0];
#pragma unroll
    for (int w = 1; w < 8; w++) gm = fmaxf(gm, red[w]);
    __syncthreads();

    float sum = 0.f;
#pragma unroll
    for (int u = 0; u < 16; u++) {
        x[u] = __expf(x[u] - gm);
        sum += x[u];
    }
    for (int off = 16; off > 0; off >>= 1)
        sum += __shfl_xor_sync(0xffffffffu, sum, off);
    if (lane == 0) red[wid] = sum;
    __syncthreads();
    float tot = 0.f;
#pragma unroll
    for (int w = 0; w < 8; w++) tot += red[w];
    float inv = 1.0f / tot;

    __half* ah = g_A + (size_t)row * JD;
#pragma unroll
    for (int u = 0; u < 4; u++) {
        union { __half v[4]; uint2 q; } pk;
#pragma unroll
        for (int e = 0; e < 4; e++)
            pk.v[e] = __float2half(x[u * 4 + e] * inv);
        *(uint2*)&ah[u * 1024 + t * 4] = pk.q;
    }
}

// ============================================================================
// launch
// ============================================================================
extern "C" void kernel_launch(void* const* d_in, const int* in_sizes, int n_in,
                              void* d_out, int out_size) {
    const float* emb = (const float*)d_in[0];
    const float* Wq  = (const float*)d_in[1];
    const float* Wk  = (const float*)d_in[2];
    const float* Wv  = (const float*)d_in[3];
    const float* Wo  = (const float*)d_in[4];
    float* outp = (float*)d_out;

    void *qt, *kt, *vv, *cx;
    cudaGetSymbolAddress(&qt, g_Qt);
    cudaGetSymbolAddress(&kt, g_Kt);
    cudaGetSymbolAddress(&vv, g_V);
    cudaGetSymbolAddress(&cx, g_CTX);

    cudaFuncSetAttribute(scores_mma, cudaFuncAttributeMaxDynamicSharedMemorySize, SMEM_DYN);
    cudaFuncSetAttribute(ctx_mma, cudaFuncAttributeMaxDynamicSharedMemorySize, SMEM_DYN);

    qkv_gemm<<<dim3(CH / 64, ROWS_TOT / 64), 256>>>(emb, Wq, Wk, Wv,
                                                    (__half*)qt, (__half*)kt, (__half*)vv);

    scores_mma<<<dim3(JD / 128, CH / 128, BTOT), 256, SMEM_DYN>>>();

    softmax_k<<<BTOT * CH, 256>>>();

    ctx_mma<<<dim3(CH / 128, NSEQ / 128, BTOT), 256, SMEM_DYN>>>();

    gemm_out<<<ROWS_TOT / 128, 256>>>((const float*)cx, Wo, outp);
}

// round 11
// speedup vs baseline: 1.0135x; 1.0135x over previous
#include <cuda_runtime.h>
#include <cuda_fp16.h>
#include <cstdint>
#include <cstddef>

#define NSEQ  2048
#define CDIM  64
#define CH    512
#define JD    4096
#define BTOT  16
#define ROWS_TOT (BTOT * NSEQ)
#define EPS_F 1e-5f
#define SCALE_F 256.0f          // operand pre-scale (2^8)

// stage (k64): A 128x64 fp16 = 16KB, B 128x64 fp16 = 16KB
#define STAGE_BYTES 32768
#define NSTG 3
#define SMEM_DYN (NSTG * STAGE_BYTES)

// ---------------- scratch ----------------
__device__ __half g_Qt[(size_t)BTOT * CH * NSEQ];    // [b][i][n], x256
__device__ __half g_Kt[(size_t)BTOT * CH * NSEQ];    // [b][j][n], x256
__device__ __half g_V [(size_t)BTOT * NSEQ * CH];    // [b][n][c], x256
__device__ float  g_S [(size_t)BTOT * CH * JD];      // scores, x2^16
__device__ __half g_A [(size_t)BTOT * CH * JD];      // attn fp16 [b][i][j]
__device__ __half g_CTXh[(size_t)BTOT * NSEQ * CH];  // ctx fp16, true scale
__device__ double g_red[BTOT * 2];

// ---------------- helpers ----------------
__device__ __forceinline__ uint32_t smem_u32(const void* p) {
    uint32_t a;
    asm("{ .reg .u64 t; cvta.to.shared.u64 t, %1; cvt.u32.u64 %0, t; }" : "=r"(a) : "l"(p));
    return a;
}
__device__ __forceinline__ void cp_async16(uint32_t s, const void* g) {
    asm volatile("cp.async.cg.shared.global [%0], [%1], 16;" :: "r"(s), "l"(g) : "memory");
}
__device__ __forceinline__ void cp_commit() {
    asm volatile("cp.async.commit_group;" ::: "memory");
}
template <int N>
__device__ __forceinline__ void cp_wait_group() {
    asm volatile("cp.async.wait_group %0;" :: "n"(N) : "memory");
}
// SW128 swizzle for 128-byte rows
__device__ __forceinline__ uint32_t swz(uint32_t off) {
    return off ^ ((off >> 3) & 0x70);
}
__device__ __forceinline__ void mma16816h(float* c, const uint32_t a[4],
                                          uint32_t b0, uint32_t b1) {
    asm volatile(
        "mma.sync.aligned.m16n8k16.row.col.f32.f16.f16.f32 "
        "{%0,%1,%2,%3}, {%4,%5,%6,%7}, {%8,%9}, {%0,%1,%2,%3};"
        : "+f"(c[0]), "+f"(c[1]), "+f"(c[2]), "+f"(c[3])
        : "r"(a[0]), "r"(a[1]), "r"(a[2]), "r"(a[3]), "r"(b0), "r"(b1));
}
__device__ __forceinline__ void ldsm4(uint32_t r[4], uint32_t addr) {
    asm volatile("ldmatrix.sync.aligned.m8n8.x4.shared.b16 {%0,%1,%2,%3}, [%4];"
                 : "=r"(r[0]), "=r"(r[1]), "=r"(r[2]), "=r"(r[3]) : "r"(addr));
}

// load 128 x 64 fp16 tile (128B rows) into SW128-swizzled smem (256 threads)
__device__ __forceinline__ void ldtile(uint32_t sdst, const char* g, size_t stride, int tid) {
#pragma unroll
    for (int t = 0; t < 4; t++) {
        int op = tid + t * 256;
        int row = op >> 3, c = op & 7;
        uint32_t off = row * 128 + c * 16;
        cp_async16(sdst + swz(off), g + (size_t)row * stride + c * 16);
    }
}

// ============================================================================
// single-term fp16 compute for one k64 stage; warp tile 64x32 (4 mt x 4 nt)
// R9 form (simple serial ldsm->mma chain; proven fastest at 2 CTAs/SM).
// baseA/baseB pre-swizzled; k-offset via XOR (row bits 5-6 zero).
// ============================================================================
__device__ __forceinline__ void compute_stage(uint32_t sA, uint32_t sB,
                                              const uint32_t baseA[4],
                                              const uint32_t baseB[2],
                                              float acc[4][4][4]) {
#pragma unroll
    for (int kk = 0; kk < 4; kk++) {
        uint32_t kb = kk * 32;
        uint32_t ah[4][4], bf[2][4];
#pragma unroll
        for (int mt = 0; mt < 4; mt++)
            ldsm4(ah[mt], sA + (baseA[mt] ^ kb));
#pragma unroll
        for (int np = 0; np < 2; np++)
            ldsm4(bf[np], sB + (baseB[np] ^ kb));
#pragma unroll
        for (int np = 0; np < 2; np++) {
#pragma unroll
            for (int h = 0; h < 2; h++) {
                uint32_t b0 = bf[np][h], b1 = bf[np][2 + h];
                int nt = np * 2 + h;
#pragma unroll
                for (int mt = 0; mt < 4; mt++)
                    mma16816h(acc[mt][nt], ah[mt], b0, b1);
            }
        }
    }
}

// ============================================================================
// scores: S[ob][i][j] = sum_n Qt[ob][i][n] * Kt[kvb][jc][n]   (x 2^16)
// CTA tile 128(i) x 128(j), grid (32, 4, 16), block 256, 2 CTAs/SM
// smem-staged coalesced epilogue + fused per-batch sum/sumsq.
// ============================================================================
__global__ void __launch_bounds__(256, 2) scores_mma() {
    extern __shared__ char dsm[];
    uint32_t sb = smem_u32(dsm);
    __shared__ double sred[8], sred2[8];

    int ob = blockIdx.z;
    int kvbase = (ob < 8) ? 8 : 0;
    int i0 = blockIdx.y << 7;
    int j0 = blockIdx.x << 7;
    int kvb = kvbase + (j0 >> 9);
    int jc0 = j0 & 511;

    int tid = threadIdx.x;
    int wid = tid >> 5, lane = tid & 31;
    int g = lane >> 2, tg = lane & 3;
    int wm = (wid & 1) * 64, wn = (wid >> 1) * 32;

    uint32_t baseA[4], baseB[2];
    uint32_t lrow = lane & 15, lcol = (lane >> 4) * 16;
#pragma unroll
    for (int mt = 0; mt < 4; mt++) baseA[mt] = swz((wm + mt * 16 + lrow) * 128 + lcol);
#pragma unroll
    for (int np = 0; np < 2; np++) baseB[np] = swz((wn + np * 16 + lrow) * 128 + lcol);

    const char* AB = (const char*)g_Qt + ((size_t)ob * CH + i0) * NSEQ * 2;
    const char* BB = (const char*)g_Kt + ((size_t)kvb * CH + jc0) * NSEQ * 2;
    const size_t st = NSEQ * 2;

    float acc[4][4][4];
#pragma unroll
    for (int a = 0; a < 4; a++)
#pragma unroll
        for (int b = 0; b < 4; b++)
#pragma unroll
            for (int c = 0; c < 4; c++) acc[a][b][c] = 0.f;

    const int NCH = NSEQ / 64;   // 32

    auto load_chunk = [&](int c, int stg) {
        uint32_t s = sb + stg * STAGE_BYTES;
        size_t ko = (size_t)c * 128;
        ldtile(s,         AB + ko, st, tid);
        ldtile(s + 16384, BB + ko, st, tid);
        cp_commit();
    };

    load_chunk(0, 0);
    load_chunk(1, 1);
    for (int c = 0; c < NCH; c++) {
        if (c + 1 < NCH) cp_wait_group<1>(); else cp_wait_group<0>();
        __syncthreads();
        if (c + 2 < NCH) load_chunk(c + 2, (c + 2) % NSTG);
        uint32_t s = sb + (c % NSTG) * STAGE_BYTES;
        compute_stage(s, s + 16384, baseA, baseB, acc);
    }

    // epilogue: stage tile in smem, then coalesced float4 writes + sum/sumsq
    __syncthreads();
    float* stage = (float*)dsm;   // [128][132]
#pragma unroll
    for (int mt = 0; mt < 4; mt++) {
#pragma unroll
        for (int nt = 0; nt < 4; nt++) {
            int row = wm + mt * 16 + g;
            int col = wn + nt * 8 + tg * 2;
            *(float2*)&stage[row * 132 + col] =
                make_float2(acc[mt][nt][0], acc[mt][nt][1]);
            *(float2*)&stage[(row + 8) * 132 + col] =
                make_float2(acc[mt][nt][2], acc[mt][nt][3]);
        }
    }
    __syncthreads();

    float* gout = g_S + (size_t)ob * CH * JD;
    float s1 = 0.f, s2 = 0.f;
#pragma unroll
    for (int k = 0; k < 16; k++) {
        int idx = tid + k * 256;
        int row = idx >> 5, c4 = (idx & 31) * 4;
        float4 v = *(float4*)&stage[row * 132 + c4];
        *(float4*)&gout[(size_t)(i0 + row) * JD + j0 + c4] = v;
        s1 += v.x + v.y + v.z + v.w;
        s2 += v.x * v.x + v.y * v.y + v.z * v.z + v.w * v.w;
    }
    double d1 = (double)s1, d2 = (double)s2;
    for (int off = 16; off > 0; off >>= 1) {
        d1 += __shfl_down_sync(0xffffffffu, d1, off);
        d2 += __shfl_down_sync(0xffffffffu, d2, off);
    }
    if (lane == 0) { sred[wid] = d1; sred2[wid] = d2; }
    __syncthreads();
    if (tid == 0) {
        double t1 = 0.0, t2 = 0.0;
#pragma unroll
        for (int w = 0; w < 8; w++) { t1 += sred[w]; t2 += sred2[w]; }
        atomicAdd(&g_red[2 * ob], t1);
        atomicAdd(&g_red[2 * ob + 1], t2);
    }
}

// ============================================================================
// ctx: CTX[ob][n][i] = sum_j V[kvb(j)][n][jc] * attn[ob][i][j]
// CTA tile 128(n) x 128(i), grid (4, 16, 16), block 256, 2 CTAs/SM
// smem-staged epilogue, CTX emitted as fp16 (true scale), coalesced.
// ============================================================================
__global__ void __launch_bounds__(256, 2) ctx_mma() {
    extern __shared__ char dsm[];
    uint32_t sb = smem_u32(dsm);

    int ob = blockIdx.z;
    int kvbase = (ob < 8) ? 8 : 0;
    int i0 = blockIdx.x << 7;
    int n0 = blockIdx.y << 7;

    int tid = threadIdx.x;
    int wid = tid >> 5, lane = tid & 31;
    int g = lane >> 2, tg = lane & 3;
    int wm = (wid & 1) * 64, wn = (wid >> 1) * 32;

    uint32_t baseA[4], baseB[2];
    uint32_t lrow = lane & 15, lcol = (lane >> 4) * 16;
#pragma unroll
    for (int mt = 0; mt < 4; mt++) baseA[mt] = swz((wm + mt * 16 + lrow) * 128 + lcol);
#pragma unroll
    for (int np = 0; np < 2; np++) baseB[np] = swz((wn + np * 16 + lrow) * 128 + lcol);

    const char* BB = (const char*)g_A + ((size_t)ob * CH + i0) * JD * 2;

    float acc[4][4][4];
#pragma unroll
    for (int a = 0; a < 4; a++)
#pragma unroll
        for (int b = 0; b < 4; b++)
#pragma unroll
            for (int c = 0; c < 4; c++) acc[a][b][c] = 0.f;

    const int NCH = JD / 64;   // 64

    auto load_chunk = [&](int c, int stg) {
        uint32_t s = sb + stg * STAGE_BYTES;
        int j0c = c * 64;
        int kvb = kvbase + (j0c >> 9);
        int jc0 = j0c & 511;
        const char* Ap = (const char*)g_V + (((size_t)kvb * NSEQ + n0) * CH + jc0) * 2;
        ldtile(s,         Ap, CH * 2, tid);
        ldtile(s + 16384, BB + (size_t)j0c * 2, JD * 2, tid);
        cp_commit();
    };

    load_chunk(0, 0);
    load_chunk(1, 1);
    for (int c = 0; c < NCH; c++) {
        if (c + 1 < NCH) cp_wait_group<1>(); else cp_wait_group<0>();
        __syncthreads();
        if (c + 2 < NCH) load_chunk(c + 2, (c + 2) % NSTG);
        uint32_t s = sb + (c % NSTG) * STAGE_BYTES;
        compute_stage(s, s + 16384, baseA, baseB, acc);
    }

    // epilogue: stage fp16 tile in smem, coalesced uint4 writes
    __syncthreads();
    __half* stageh = (__half*)dsm;   // [128][136]
    const float ds = 1.0f / SCALE_F;
#pragma unroll
    for (int mt = 0; mt < 4; mt++) {
#pragma unroll
        for (int nt = 0; nt < 4; nt++) {
            int row = wm + mt * 16 + g;
            int col = wn + nt * 8 + tg * 2;
            *(__half2*)&stageh[row * 136 + col] =
                __floats2half2_rn(acc[mt][nt][0] * ds, acc[mt][nt][1] * ds);
            *(__half2*)&stageh[(row + 8) * 136 + col] =
                __floats2half2_rn(acc[mt][nt][2] * ds, acc[mt][nt][3] * ds);
        }
    }
    __syncthreads();

    __half* gout = g_CTXh + (size_t)ob * NSEQ * CH;
#pragma unroll
    for (int k = 0; k < 8; k++) {
        int idx = tid + k * 256;
        int row = idx >> 4, c8 = (idx & 15) * 8;
        uint4 v = *(uint4*)&stageh[row * 136 + c8];
        *(uint4*)&gout[(size_t)(n0 + row) * CH + i0 + c8] = v;
    }
}

// ============================================================================
// fused QKV projection: Qt/Kt (transposed) + V (row) from one emb tile read.
// grid (CH/64=8, ROWS_TOT/64=512), 256 threads. Also zeroes g_red.
// ============================================================================
__global__ void __launch_bounds__(256) qkv_gemm(const float* __restrict__ A,
                                                const float* __restrict__ BmQ,
                                                const float* __restrict__ BmK,
                                                const float* __restrict__ BmV,
                                                __half* __restrict__ Qt,
                                                __half* __restrict__ Kt,
                                                __half* __restrict__ Vv) {
    __shared__ __align__(16) float As[16][68];
    __shared__ __align__(16) float BsQ[16][64], BsK[16][64], BsV[16][64];
    const int K = CDIM, N = CH;
    int bm = blockIdx.y * 64, bn = blockIdx.x * 64;
    int tid = threadIdx.x;

    if (blockIdx.x == 0 && blockIdx.y == 0 && tid < BTOT * 2)
        g_red[tid] = 0.0;

    int tx = tid & 15, ty = tid >> 4;
    int am = tid >> 2, ak = (tid & 3) << 2;
    int br = tid >> 4, bc = (tid & 15) << 2;
    const float* Aptr = A + (size_t)(bm + am) * K + ak;

    float aq[4][4], akk[4][4], av_[4][4];
#pragma unroll
    for (int i = 0; i < 4; i++)
#pragma unroll
        for (int j = 0; j < 4; j++) { aq[i][j] = 0.f; akk[i][j] = 0.f; av_[i][j] = 0.f; }

    for (int k0 = 0; k0 < K; k0 += 16) {
        float4 avv = *(const float4*)(Aptr + k0);
        As[ak + 0][am] = avv.x; As[ak + 1][am] = avv.y;
        As[ak + 2][am] = avv.z; As[ak + 3][am] = avv.w;
        size_t boff = (size_t)(k0 + br) * N + bn + bc;
        *(float4*)&BsQ[br][bc] = *(const float4*)&BmQ[boff];
        *(float4*)&BsK[br][bc] = *(const float4*)&BmK[boff];
        *(float4*)&BsV[br][bc] = *(const float4*)&BmV[boff];
        __syncthreads();
#pragma unroll
        for (int kk = 0; kk < 16; kk++) {
            float a0 = As[kk][ty * 4 + 0], a1 = As[kk][ty * 4 + 1];
            float a2 = As[kk][ty * 4 + 2], a3 = As[kk][ty * 4 + 3];
#pragma unroll
            for (int j = 0; j < 4; j++) {
                float bq = BsQ[kk][tx * 4 + j];
                float bk = BsK[kk][tx * 4 + j];
                float bv = BsV[kk][tx * 4 + j];
                aq[0][j] += a0 * bq; aq[1][j] += a1 * bq; aq[2][j] += a2 * bq; aq[3][j] += a3 * bq;
                akk[0][j] += a0 * bk; akk[1][j] += a1 * bk; akk[2][j] += a2 * bk; akk[3][j] += a3 * bk;
                av_[0][j] += a0 * bv; av_[1][j] += a1 * bv; av_[2][j] += a2 * bv; av_[3][j] += a3 * bv;
            }
        }
        __syncthreads();
    }

    // Qt / Kt transposed epilogue: out[b][col][n]
    {
        int b = bm >> 11;
        int nloc = (bm & 2047) + ty * 4;
#pragma unroll
        for (int j = 0; j < 4; j++) {
            int col = bn + tx * 4 + j;
            union { __half v[4]; uint2 u; } pq, pk;
#pragma unroll
            for (int i = 0; i < 4; i++) {
                pq.v[i] = __float2half(aq[i][j] * SCALE_F);
                pk.v[i] = __float2half(akk[i][j] * SCALE_F);
            }
            size_t off = (size_t)b * (CH * NSEQ) + (size_t)col * NSEQ + nloc;
            *(uint2*)&Qt[off] = pq.u;
            *(uint2*)&Kt[off] = pk.u;
        }
    }
    // V row-major epilogue
#pragma unroll
    for (int i = 0; i < 4; i++) {
        int m = bm + ty * 4 + i;
        union { __half v[4]; uint2 u; } pv;
#pragma unroll
        for (int j = 0; j < 4; j++)
            pv.v[j] = __float2half(av_[i][j] * SCALE_F);
        *(uint2*)&Vv[(size_t)m * CH + bn + tx * 4] = pv.u;
    }
}

// ============================================================================
// out projection: C[M,64] = CTXh[M,512] @ Wo[512,64]; 128x64 tile, fp16 A.
// ============================================================================
__global__ void __launch_bounds__(256) gemm_out(const __half* __restrict__ A,
                                                const float* __restrict__ Bm,
                                                float* __restrict__ Cm) {
    __shared__ __align__(16) float As[16][132];
    __shared__ __align__(16) float Bs[16][64];
    const int K = CH, N = CDIM;
    int bm = blockIdx.x * 128;
    int tid = threadIdx.x;
    int tx = tid & 15, ty = tid >> 4;
    int am = tid >> 2, ak = (tid & 3) << 2;
    int br = tid >> 4, bc = (tid & 15) << 2;

    float acc[8][4];
#pragma unroll
    for (int i = 0; i < 8; i++)
#pragma unroll
        for (int j = 0; j < 4; j++) acc[i][j] = 0.f;

    for (int k0 = 0; k0 < K; k0 += 16) {
        // 4 halves per thread per row-group (uint2)
        uint2 u0 = *(const uint2*)&A[(size_t)(bm + am) * K + k0 + ak];
        uint2 u1 = *(const uint2*)&A[(size_t)(bm + am + 64) * K + k0 + ak];
        float2 f00 = __half22float2(*(__half2*)&u0.x);
        float2 f01 = __half22float2(*(__half2*)&u0.y);
        float2 f10 = __half22float2(*(__half2*)&u1.x);
        float2 f11 = __half22float2(*(__half2*)&u1.y);
        As[ak + 0][am] = f00.x; As[ak + 1][am] = f00.y;
        As[ak + 2][am] = f01.x; As[ak + 3][am] = f01.y;
        As[ak + 0][am + 64] = f10.x; As[ak + 1][am + 64] = f10.y;
        As[ak + 2][am + 64] = f11.x; As[ak + 3][am + 64] = f11.y;
        *(float4*)&Bs[br][bc] = *(const float4*)&Bm[(size_t)(k0 + br) * N + bc];
        __syncthreads();
#pragma unroll
        for (int kk = 0; kk < 16; kk++) {
            float a[8], b[4];
            *(float4*)&a[0] = *(float4*)&As[kk][ty * 8];
            *(float4*)&a[4] = *(float4*)&As[kk][ty * 8 + 4];
            *(float4*)&b[0] = *(float4*)&Bs[kk][tx * 4];
#pragma unroll
            for (int i = 0; i < 8; i++)
#pragma unroll
                for (int j = 0; j < 4; j++) acc[i][j] += a[i] * b[j];
        }
        __syncthreads();
    }
#pragma unroll
    for (int i = 0; i < 8; i++) {
        float4 v = make_float4(acc[i][0], acc[i][1], acc[i][2], acc[i][3]);
        *(float4*)&Cm[(size_t)(bm + ty * 8 + i) * N + tx * 4] = v;
    }
}

// ============================================================================
// softmax (fused rstd finalize): scale + softmax over j, write attn fp16.
// ============================================================================
__global__ void __launch_bounds__(256) softmax_k() {
    int row = blockIdx.x;
    int b = row >> 9;
    __shared__ float srstd;
    __shared__ float red[8];
    int t = threadIdx.x;

    if (t == 0) {
        const double SC = 65536.0;   // scores are scaled by 2^16
        double n = (double)CH * (double)JD;
        double mean = g_red[2 * b] / (n * SC);
        double var  = g_red[2 * b + 1] / (n * SC * SC) - mean * mean;
        srstd = rsqrtf((float)var + EPS_F) / (float)SC;
    }

    const float* p = g_S + (size_t)row * JD;
    float4 xv[4];
#pragma unroll
    for (int u = 0; u < 4; u++)
        xv[u] = *(const float4*)&p[u * 1024 + t * 4];
    __syncthreads();
    float rstd = srstd;

    float* x = (float*)xv;
    float mx = -1e30f;
#pragma unroll
    for (int u = 0; u < 16; u++) {
        x[u] *= rstd;
        mx = fmaxf(mx, x[u]);
    }
    for (int off = 16; off > 0; off >>= 1)
        mx = fmaxf(mx, __shfl_xor_sync(0xffffffffu, mx, off));
    int lane = t & 31, wid = t >> 5;
    if (lane == 0) red[wid] = mx;
    __syncthreads();
    float gm = red[0];
#pragma unroll
    for (int w = 1; w < 8; w++) gm = fmaxf(gm, red[w]);
    __syncthreads();

    float sum = 0.f;
#pragma unroll
    for (int u = 0; u < 16; u++) {
        x[u] = __expf(x[u] - gm);
        sum += x[u];
    }
    for (int off = 16; off > 0; off >>= 1)
        sum += __shfl_xor_sync(0xffffffffu, sum, off);
    if (lane == 0) red[wid] = sum;
    __syncthreads();
    float tot = 0.f;
#pragma unroll
    for (int w = 0; w < 8; w++) tot += red[w];
    float inv = 1.0f / tot;

    __half* ah = g_A + (size_t)row * JD;
#pragma unroll
    for (int u = 0; u < 4; u++) {
        union { __half v[4]; uint2 q; } pk;
#pragma unroll
        for (int e = 0; e < 4; e++)
            pk.v[e] = __float2half(x[u * 4 + e] * inv);
        *(uint2*)&ah[u * 1024 + t * 4] = pk.q;
    }
}

// ============================================================================
// launch
// ============================================================================
extern "C" void kernel_launch(void* const* d_in, const int* in_sizes, int n_in,
                              void* d_out, int out_size) {
    const float* emb = (const float*)d_in[0];
    const float* Wq  = (const float*)d_in[1];
    const float* Wk  = (const float*)d_in[2];
    const float* Wv  = (const float*)d_in[3];
    const float* Wo  = (const float*)d_in[4];
    float* outp = (float*)d_out;

    void *qt, *kt, *vv, *cx;
    cudaGetSymbolAddress(&qt, g_Qt);
    cudaGetSymbolAddress(&kt, g_Kt);
    cudaGetSymbolAddress(&vv, g_V);
    cudaGetSymbolAddress(&cx, g_CTXh);

    cudaFuncSetAttribute(scores_mma, cudaFuncAttributeMaxDynamicSharedMemorySize, SMEM_DYN);
    cudaFuncSetAttribute(ctx_mma, cudaFuncAttributeMaxDynamicSharedMemorySize, SMEM_DYN);

    qkv_gemm<<<dim3(CH / 64, ROWS_TOT / 64), 256>>>(emb, Wq, Wk, Wv,
                                                    (__half*)qt, (__half*)kt, (__half*)vv);

    scores_mma<<<dim3(JD / 128, CH / 128, BTOT), 256, SMEM_DYN>>>();

    softmax_k<<<BTOT * CH, 256>>>();

    ctx_mma<<<dim3(CH / 128, NSEQ / 128, BTOT), 256, SMEM_DYN>>>();

    gemm_out<<<ROWS_TOT / 128, 256>>>((const __half*)cx, Wo, outp);
}

// round 12
// speedup vs baseline: 1.0334x; 1.0196x over previous
#include <cuda_runtime.h>
#include <cuda_fp16.h>
#include <cstdint>
#include <cstddef>

#define NSEQ  2048
#define CDIM  64
#define CH    512
#define JD    4096
#define BTOT  16
#define ROWS_TOT (BTOT * NSEQ)
#define EPS_F 1e-5f
#define SCALE_F 256.0f          // operand pre-scale (2^8)

// stage (k64): A 128x64 fp16 = 16KB, B 128x64 fp16 = 16KB
#define STAGE_BYTES 32768
#define NSTG 3
#define SMEM_DYN (NSTG * STAGE_BYTES)

// ---------------- scratch ----------------
__device__ __half g_Qt[(size_t)BTOT * CH * NSEQ];    // [b][i][n], x256
__device__ __half g_Kt[(size_t)BTOT * CH * NSEQ];    // [b][j][n], x256
__device__ __half g_V [(size_t)BTOT * NSEQ * CH];    // [b][n][c], x256
__device__ float  g_S [(size_t)BTOT * CH * JD];      // scores, x2^16
__device__ __half g_A [(size_t)BTOT * CH * JD];      // attn fp16 [b][i][j]
__device__ float  g_CTX[(size_t)BTOT * NSEQ * CH];   // true scale
__device__ double g_red[BTOT * 2];

// ---------------- helpers ----------------
__device__ __forceinline__ uint32_t smem_u32(const void* p) {
    uint32_t a;
    asm("{ .reg .u64 t; cvta.to.shared.u64 t, %1; cvt.u32.u64 %0, t; }" : "=r"(a) : "l"(p));
    return a;
}
__device__ __forceinline__ void cp_async16(uint32_t s, const void* g) {
    asm volatile("cp.async.cg.shared.global [%0], [%1], 16;" :: "r"(s), "l"(g) : "memory");
}
__device__ __forceinline__ void cp_commit() {
    asm volatile("cp.async.commit_group;" ::: "memory");
}
template <int N>
__device__ __forceinline__ void cp_wait_group() {
    asm volatile("cp.async.wait_group %0;" :: "n"(N) : "memory");
}
// SW128 swizzle for 128-byte rows
__device__ __forceinline__ uint32_t swz(uint32_t off) {
    return off ^ ((off >> 3) & 0x70);
}
__device__ __forceinline__ void mma16816h(float* c, const uint32_t a[4],
                                          uint32_t b0, uint32_t b1) {
    asm volatile(
        "mma.sync.aligned.m16n8k16.row.col.f32.f16.f16.f32 "
        "{%0,%1,%2,%3}, {%4,%5,%6,%7}, {%8,%9}, {%0,%1,%2,%3};"
        : "+f"(c[0]), "+f"(c[1]), "+f"(c[2]), "+f"(c[3])
        : "r"(a[0]), "r"(a[1]), "r"(a[2]), "r"(a[3]), "r"(b0), "r"(b1));
}
__device__ __forceinline__ void ldsm4(uint32_t r[4], uint32_t addr) {
    asm volatile("ldmatrix.sync.aligned.m8n8.x4.shared.b16 {%0,%1,%2,%3}, [%4];"
                 : "=r"(r[0]), "=r"(r[1]), "=r"(r[2]), "=r"(r[3]) : "r"(addr));
}

// load 128 x 64 fp16 tile (128B rows) into SW128-swizzled smem (256 threads)
__device__ __forceinline__ void ldtile(uint32_t sdst, const char* g, size_t stride, int tid) {
#pragma unroll
    for (int t = 0; t < 4; t++) {
        int op = tid + t * 256;
        int row = op >> 3, c = op & 7;
        uint32_t off = row * 128 + c * 16;
        cp_async16(sdst + swz(off), g + (size_t)row * stride + c * 16);
    }
}

// ============================================================================
// single-term fp16 compute for one k64 stage; warp tile 64x32 (4 mt x 4 nt)
// R9 form (simple serial ldsm->mma chain; proven fastest at 2 CTAs/SM).
// ============================================================================
__device__ __forceinline__ void compute_stage(uint32_t sA, uint32_t sB,
                                              const uint32_t baseA[4],
                                              const uint32_t baseB[2],
                                              float acc[4][4][4]) {
#pragma unroll
    for (int kk = 0; kk < 4; kk++) {
        uint32_t kb = kk * 32;
        uint32_t ah[4][4], bf[2][4];
#pragma unroll
        for (int mt = 0; mt < 4; mt++)
            ldsm4(ah[mt], sA + (baseA[mt] ^ kb));
#pragma unroll
        for (int np = 0; np < 2; np++)
            ldsm4(bf[np], sB + (baseB[np] ^ kb));
#pragma unroll
        for (int np = 0; np < 2; np++) {
#pragma unroll
            for (int h = 0; h < 2; h++) {
                uint32_t b0 = bf[np][h], b1 = bf[np][2 + h];
                int nt = np * 2 + h;
#pragma unroll
                for (int mt = 0; mt < 4; mt++)
                    mma16816h(acc[mt][nt], ah[mt], b0, b1);
            }
        }
    }
}

// ============================================================================
// scores: S[ob][i][j] = sum_n Qt[ob][i][n] * Kt[kvb][jc][n]   (x 2^16)
// CTA tile 128(i) x 128(j), grid (32, 4, 16), block 256, 2 CTAs/SM
// R9 direct-fragment epilogue + fused per-batch sum/sumsq.
// ============================================================================
__global__ void __launch_bounds__(256, 2) scores_mma() {
    extern __shared__ char dsm[];
    uint32_t sb = smem_u32(dsm);
    __shared__ double sred[8], sred2[8];

    int ob = blockIdx.z;
    int kvbase = (ob < 8) ? 8 : 0;
    int i0 = blockIdx.y << 7;
    int j0 = blockIdx.x << 7;
    int kvb = kvbase + (j0 >> 9);
    int jc0 = j0 & 511;

    int tid = threadIdx.x;
    int wid = tid >> 5, lane = tid & 31;
    int g = lane >> 2, tg = lane & 3;
    int wm = (wid & 1) * 64, wn = (wid >> 1) * 32;

    uint32_t baseA[4], baseB[2];
    uint32_t lrow = lane & 15, lcol = (lane >> 4) * 16;
#pragma unroll
    for (int mt = 0; mt < 4; mt++) baseA[mt] = swz((wm + mt * 16 + lrow) * 128 + lcol);
#pragma unroll
    for (int np = 0; np < 2; np++) baseB[np] = swz((wn + np * 16 + lrow) * 128 + lcol);

    const char* AB = (const char*)g_Qt + ((size_t)ob * CH + i0) * NSEQ * 2;
    const char* BB = (const char*)g_Kt + ((size_t)kvb * CH + jc0) * NSEQ * 2;
    const size_t st = NSEQ * 2;

    float acc[4][4][4];
#pragma unroll
    for (int a = 0; a < 4; a++)
#pragma unroll
        for (int b = 0; b < 4; b++)
#pragma unroll
            for (int c = 0; c < 4; c++) acc[a][b][c] = 0.f;

    const int NCH = NSEQ / 64;   // 32

    auto load_chunk = [&](int c, int stg) {
        uint32_t s = sb + stg * STAGE_BYTES;
        size_t ko = (size_t)c * 128;
        ldtile(s,         AB + ko, st, tid);
        ldtile(s + 16384, BB + ko, st, tid);
        cp_commit();
    };

    load_chunk(0, 0);
    load_chunk(1, 1);
    for (int c = 0; c < NCH; c++) {
        if (c + 1 < NCH) cp_wait_group<1>(); else cp_wait_group<0>();
        __syncthreads();
        if (c + 2 < NCH) load_chunk(c + 2, (c + 2) % NSTG);
        uint32_t s = sb + (c % NSTG) * STAGE_BYTES;
        compute_stage(s, s + 16384, baseA, baseB, acc);
    }

    // write scores directly from fragments + fused sum/sumsq
    float* gout = g_S + (size_t)ob * CH * JD;
    float s1 = 0.f, s2 = 0.f;
#pragma unroll
    for (int mt = 0; mt < 4; mt++) {
#pragma unroll
        for (int nt = 0; nt < 4; nt++) {
            int row = i0 + wm + mt * 16 + g;
            int col = j0 + wn + nt * 8 + tg * 2;
            float v0 = acc[mt][nt][0], v1 = acc[mt][nt][1];
            float v2 = acc[mt][nt][2], v3 = acc[mt][nt][3];
            *(float2*)&gout[(size_t)row * JD + col] = make_float2(v0, v1);
            *(float2*)&gout[(size_t)(row + 8) * JD + col] = make_float2(v2, v3);
            s1 += v0 + v1 + v2 + v3;
            s2 += v0 * v0 + v1 * v1 + v2 * v2 + v3 * v3;
        }
    }
    double d1 = (double)s1, d2 = (double)s2;
    for (int off = 16; off > 0; off >>= 1) {
        d1 += __shfl_down_sync(0xffffffffu, d1, off);
        d2 += __shfl_down_sync(0xffffffffu, d2, off);
    }
    if (lane == 0) { sred[wid] = d1; sred2[wid] = d2; }
    __syncthreads();
    if (tid == 0) {
        double t1 = 0.0, t2 = 0.0;
#pragma unroll
        for (int w = 0; w < 8; w++) { t1 += sred[w]; t2 += sred2[w]; }
        atomicAdd(&g_red[2 * ob], t1);
        atomicAdd(&g_red[2 * ob + 1], t2);
    }
}

// ============================================================================
// ctx: CTX[ob][n][i] = sum_j V[kvb(j)][n][jc] * attn[ob][i][j]
// CTA tile 128(n) x 128(i), grid (4, 16, 16), block 256, 2 CTAs/SM
// R9 direct-fragment fp32 epilogue.
// ============================================================================
__global__ void __launch_bounds__(256, 2) ctx_mma() {
    extern __shared__ char dsm[];
    uint32_t sb = smem_u32(dsm);

    int ob = blockIdx.z;
    int kvbase = (ob < 8) ? 8 : 0;
    int i0 = blockIdx.x << 7;
    int n0 = blockIdx.y << 7;

    int tid = threadIdx.x;
    int wid = tid >> 5, lane = tid & 31;
    int g = lane >> 2, tg = lane & 3;
    int wm = (wid & 1) * 64, wn = (wid >> 1) * 32;

    uint32_t baseA[4], baseB[2];
    uint32_t lrow = lane & 15, lcol = (lane >> 4) * 16;
#pragma unroll
    for (int mt = 0; mt < 4; mt++) baseA[mt] = swz((wm + mt * 16 + lrow) * 128 + lcol);
#pragma unroll
    for (int np = 0; np < 2; np++) baseB[np] = swz((wn + np * 16 + lrow) * 128 + lcol);

    const char* BB = (const char*)g_A + ((size_t)ob * CH + i0) * JD * 2;

    float acc[4][4][4];
#pragma unroll
    for (int a = 0; a < 4; a++)
#pragma unroll
        for (int b = 0; b < 4; b++)
#pragma unroll
            for (int c = 0; c < 4; c++) acc[a][b][c] = 0.f;

    const int NCH = JD / 64;   // 64

    auto load_chunk = [&](int c, int stg) {
        uint32_t s = sb + stg * STAGE_BYTES;
        int j0c = c * 64;
        int kvb = kvbase + (j0c >> 9);
        int jc0 = j0c & 511;
        const char* Ap = (const char*)g_V + (((size_t)kvb * NSEQ + n0) * CH + jc0) * 2;
        ldtile(s,         Ap, CH * 2, tid);
        ldtile(s + 16384, BB + (size_t)j0c * 2, JD * 2, tid);
        cp_commit();
    };

    load_chunk(0, 0);
    load_chunk(1, 1);
    for (int c = 0; c < NCH; c++) {
        if (c + 1 < NCH) cp_wait_group<1>(); else cp_wait_group<0>();
        __syncthreads();
        if (c + 2 < NCH) load_chunk(c + 2, (c + 2) % NSTG);
        uint32_t s = sb + (c % NSTG) * STAGE_BYTES;
        compute_stage(s, s + 16384, baseA, baseB, acc);
    }

    const float ds = 1.0f / SCALE_F;   // undo V pre-scale
    float* gout = g_CTX + (size_t)ob * NSEQ * CH;
#pragma unroll
    for (int mt = 0; mt < 4; mt++) {
#pragma unroll
        for (int nt = 0; nt < 4; nt++) {
            int row = n0 + wm + mt * 16 + g;
            int col = i0 + wn + nt * 8 + tg * 2;
            *(float2*)&gout[(size_t)row * CH + col] =
                make_float2(acc[mt][nt][0] * ds, acc[mt][nt][1] * ds);
            *(float2*)&gout[(size_t)(row + 8) * CH + col] =
                make_float2(acc[mt][nt][2] * ds, acc[mt][nt][3] * ds);
        }
    }
}

// ============================================================================
// fused QKV projection: 128x64 tile, 8x4 per thread x 3 outputs.
// grid (CH/64=8, ROWS_TOT/128=256), 256 threads. Also zeroes g_red.
// ============================================================================
__global__ void __launch_bounds__(256) qkv_gemm(const float* __restrict__ A,
                                                const float* __restrict__ BmQ,
                                                const float* __restrict__ BmK,
                                                const float* __restrict__ BmV,
                                                __half* __restrict__ Qt,
                                                __half* __restrict__ Kt,
                                                __half* __restrict__ Vv) {
    __shared__ __align__(16) float As[16][132];
    __shared__ __align__(16) float BsQ[16][64], BsK[16][64], BsV[16][64];
    const int K = CDIM, N = CH;
    int bm = blockIdx.y * 128, bn = blockIdx.x * 64;
    int tid = threadIdx.x;

    if (blockIdx.x == 0 && blockIdx.y == 0 && tid < BTOT * 2)
        g_red[tid] = 0.0;

    int tx = tid & 15, ty = tid >> 4;
    int br = tid >> 4, bc = (tid & 15) << 2;

    float aq[8][4], akk[8][4], av_[8][4];
#pragma unroll
    for (int i = 0; i < 8; i++)
#pragma unroll
        for (int j = 0; j < 4; j++) { aq[i][j] = 0.f; akk[i][j] = 0.f; av_[i][j] = 0.f; }

    for (int k0 = 0; k0 < K; k0 += 16) {
        // A tile: 128 rows x 16 cols -> As[k][m]; 512 float4, 2 per thread
#pragma unroll
        for (int t = 0; t < 2; t++) {
            int op = tid + t * 256;
            int row = op >> 2, c = (op & 3) * 4;
            float4 v = *(const float4*)&A[(size_t)(bm + row) * K + k0 + c];
            As[c + 0][row] = v.x; As[c + 1][row] = v.y;
            As[c + 2][row] = v.z; As[c + 3][row] = v.w;
        }
        size_t boff = (size_t)(k0 + br) * N + bn + bc;
        *(float4*)&BsQ[br][bc] = *(const float4*)&BmQ[boff];
        *(float4*)&BsK[br][bc] = *(const float4*)&BmK[boff];
        *(float4*)&BsV[br][bc] = *(const float4*)&BmV[boff];
        __syncthreads();
#pragma unroll
        for (int kk = 0; kk < 16; kk++) {
            float a[8];
            *(float4*)&a[0] = *(float4*)&As[kk][ty * 8];
            *(float4*)&a[4] = *(float4*)&As[kk][ty * 8 + 4];
            float bq[4], bk[4], bv[4];
            *(float4*)&bq[0] = *(float4*)&BsQ[kk][tx * 4];
            *(float4*)&bk[0] = *(float4*)&BsK[kk][tx * 4];
            *(float4*)&bv[0] = *(float4*)&BsV[kk][tx * 4];
#pragma unroll
            for (int i = 0; i < 8; i++)
#pragma unroll
                for (int j = 0; j < 4; j++) {
                    aq[i][j]  += a[i] * bq[j];
                    akk[i][j] += a[i] * bk[j];
                    av_[i][j] += a[i] * bv[j];
                }
        }
        __syncthreads();
    }

    // Qt / Kt transposed epilogue: out[b][col][n], 8 consecutive n -> uint4
    {
        int b = bm >> 11;
        int nloc = (bm & 2047) + ty * 8;
#pragma unroll
        for (int j = 0; j < 4; j++) {
            int col = bn + tx * 4 + j;
            union { __half v[8]; uint4 u; } pq, pk;
#pragma unroll
            for (int i = 0; i < 8; i++) {
                pq.v[i] = __float2half(aq[i][j] * SCALE_F);
                pk.v[i] = __float2half(akk[i][j] * SCALE_F);
            }
            size_t off = (size_t)b * (CH * NSEQ) + (size_t)col * NSEQ + nloc;
            *(uint4*)&Qt[off] = pq.u;
            *(uint4*)&Kt[off] = pk.u;
        }
    }
    // V row-major epilogue
#pragma unroll
    for (int i = 0; i < 8; i++) {
        int m = bm + ty * 8 + i;
        union { __half v[4]; uint2 u; } pv;
#pragma unroll
        for (int j = 0; j < 4; j++)
            pv.v[j] = __float2half(av_[i][j] * SCALE_F);
        *(uint2*)&Vv[(size_t)m * CH + bn + tx * 4] = pv.u;
    }
}

// ============================================================================
// out projection fp32: C[M,64] = CTX[M,512] @ Wo[512,64]; 128x64 tile.
// ============================================================================
__global__ void __launch_bounds__(256) gemm_out(const float* __restrict__ A,
                                                const float* __restrict__ Bm,
                                                float* __restrict__ Cm) {
    __shared__ __align__(16) float As[16][132];
    __shared__ __align__(16) float Bs[16][64];
    const int K = CH, N = CDIM;
    int bm = blockIdx.x * 128;
    int tid = threadIdx.x;
    int tx = tid & 15, ty = tid >> 4;
    int am = tid >> 2, ak = (tid & 3) << 2;
    int br = tid >> 4, bc = (tid & 15) << 2;

    float acc[8][4];
#pragma unroll
    for (int i = 0; i < 8; i++)
#pragma unroll
        for (int j = 0; j < 4; j++) acc[i][j] = 0.f;

    for (int k0 = 0; k0 < K; k0 += 16) {
        float4 a0v = *(const float4*)&A[(size_t)(bm + am) * K + k0 + ak];
        float4 a1v = *(const float4*)&A[(size_t)(bm + am + 64) * K + k0 + ak];
        As[ak + 0][am] = a0v.x; As[ak + 1][am] = a0v.y;
        As[ak + 2][am] = a0v.z; As[ak + 3][am] = a0v.w;
        As[ak + 0][am + 64] = a1v.x; As[ak + 1][am + 64] = a1v.y;
        As[ak + 2][am + 64] = a1v.z; As[ak + 3][am + 64] = a1v.w;
        *(float4*)&Bs[br][bc] = *(const float4*)&Bm[(size_t)(k0 + br) * N + bc];
        __syncthreads();
#pragma unroll
        for (int kk = 0; kk < 16; kk++) {
            float a[8], b[4];
            *(float4*)&a[0] = *(float4*)&As[kk][ty * 8];
            *(float4*)&a[4] = *(float4*)&As[kk][ty * 8 + 4];
            *(float4*)&b[0] = *(float4*)&Bs[kk][tx * 4];
#pragma unroll
            for (int i = 0; i < 8; i++)
#pragma unroll
                for (int j = 0; j < 4; j++) acc[i][j] += a[i] * b[j];
        }
        __syncthreads();
    }
#pragma unroll
    for (int i = 0; i < 8; i++) {
        float4 v = make_float4(acc[i][0], acc[i][1], acc[i][2], acc[i][3]);
        *(float4*)&Cm[(size_t)(bm + ty * 8 + i) * N + tx * 4] = v;
    }
}

// ============================================================================
// softmax (fused rstd finalize): scale + softmax over j, write attn fp16.
// ============================================================================
__global__ void __launch_bounds__(256) softmax_k() {
    int row = blockIdx.x;
    int b = row >> 9;
    __shared__ float srstd;
    __shared__ float red[8];
    int t = threadIdx.x;

    if (t == 0) {
        const double SC = 65536.0;   // scores are scaled by 2^16
        double n = (double)CH * (double)JD;
        double mean = g_red[2 * b] / (n * SC);
        double var  = g_red[2 * b + 1] / (n * SC * SC) - mean * mean;
        srstd = rsqrtf((float)var + EPS_F) / (float)SC;
    }

    const float* p = g_S + (size_t)row * JD;
    float4 xv[4];
#pragma unroll
    for (int u = 0; u < 4; u++)
        xv[u] = *(const float4*)&p[u * 1024 + t * 4];
    __syncthreads();
    float rstd = srstd;

    float* x = (float*)xv;
    float mx = -1e30f;
#pragma unroll
    for (int u = 0; u < 16; u++) {
        x[u] *= rstd;
        mx = fmaxf(mx, x[u]);
    }
    for (int off = 16; off > 0; off >>= 1)
        mx = fmaxf(mx, __shfl_xor_sync(0xffffffffu, mx, off));
    int lane = t & 31, wid = t >> 5;
    if (lane == 0) red[wid] = mx;
    __syncthreads();
    float gm = red[0];
#pragma unroll
    for (int w = 1; w < 8; w++) gm = fmaxf(gm, red[w]);
    __syncthreads();

    float sum = 0.f;
#pragma unroll
    for (int u = 0; u < 16; u++) {
        x[u] = __expf(x[u] - gm);
        sum += x[u];
    }
    for (int off = 16; off > 0; off >>= 1)
        sum += __shfl_xor_sync(0xffffffffu, sum, off);
    if (lane == 0) red[wid] = sum;
    __syncthreads();
    float tot = 0.f;
#pragma unroll
    for (int w = 0; w < 8; w++) tot += red[w];
    float inv = 1.0f / tot;

    __half* ah = g_A + (size_t)row * JD;
#pragma unroll
    for (int u = 0; u < 4; u++) {
        union { __half v[4]; uint2 q; } pk;
#pragma unroll
        for (int e = 0; e < 4; e++)
            pk.v[e] = __float2half(x[u * 4 + e] * inv);
        *(uint2*)&ah[u * 1024 + t * 4] = pk.q;
    }
}

// ============================================================================
// launch
// ============================================================================
extern "C" void kernel_launch(void* const* d_in, const int* in_sizes, int n_in,
                              void* d_out, int out_size) {
    const float* emb = (const float*)d_in[0];
    const float* Wq  = (const float*)d_in[1];
    const float* Wk  = (const float*)d_in[2];
    const float* Wv  = (const float*)d_in[3];
    const float* Wo  = (const float*)d_in[4];
    float* outp = (float*)d_out;

    void *qt, *kt, *vv, *cx;
    cudaGetSymbolAddress(&qt, g_Qt);
    cudaGetSymbolAddress(&kt, g_Kt);
    cudaGetSymbolAddress(&vv, g_V);
    cudaGetSymbolAddress(&cx, g_CTX);

    cudaFuncSetAttribute(scores_mma, cudaFuncAttributeMaxDynamicSharedMemorySize, SMEM_DYN);
    cudaFuncSetAttribute(ctx_mma, cudaFuncAttributeMaxDynamicSharedMemorySize, SMEM_DYN);

    qkv_gemm<<<dim3(CH / 64, ROWS_TOT / 128), 256>>>(emb, Wq, Wk, Wv,
                                                     (__half*)qt, (__half*)kt, (__half*)vv);

    scores_mma<<<dim3(JD / 128, CH / 128, BTOT), 256, SMEM_DYN>>>();

    softmax_k<<<BTOT * CH, 256>>>();

    ctx_mma<<<dim3(CH / 128, NSEQ / 128, BTOT), 256, SMEM_DYN>>>();

    gemm_out<<<ROWS_TOT / 128, 256>>>((const float*)cx, Wo, outp);
}

// round 13
// speedup vs baseline: 1.0893x; 1.0542x over previous
#include <cuda_runtime.h>
#include <cuda_fp16.h>
#include <cstdint>
#include <cstddef>

#define NSEQ  2048
#define CDIM  64
#define CH    512
#define JD    4096
#define BTOT  16
#define ROWS_TOT (BTOT * NSEQ)
#define EPS_F 1e-5f
#define SCALE_F 256.0f          // operand pre-scale (2^8)

// stage (k64): A 128x64 fp16 = 16KB, B 128x64 fp16 = 16KB
#define STAGE_BYTES 32768
#define NSTG 3
#define SMEM_DYN (NSTG * STAGE_BYTES)

// gemm_out stage: A 128x64 fp16 = 16KB, B 64x64 fp16 = 8KB
#define OSTAGE_BYTES 24576
#define OSMEM_DYN (NSTG * OSTAGE_BYTES)

// ---------------- scratch ----------------
__device__ __half g_Qt[(size_t)BTOT * CH * NSEQ];    // [b][i][n], x256
__device__ __half g_Kt[(size_t)BTOT * CH * NSEQ];    // [b][j][n], x256
__device__ __half g_V [(size_t)BTOT * NSEQ * CH];    // [b][n][c], x256
__device__ float  g_S [(size_t)BTOT * CH * JD];      // scores, x2^16
__device__ __half g_A [(size_t)BTOT * CH * JD];      // attn fp16 [b][i][j]
__device__ __half g_CTXh[(size_t)BTOT * NSEQ * CH];  // ctx fp16, true scale
__device__ __half g_Wot[CDIM * CH];                  // Wo^T fp16 [c][k]
__device__ double g_red[BTOT * 2];

// ---------------- helpers ----------------
__device__ __forceinline__ uint32_t smem_u32(const void* p) {
    uint32_t a;
    asm("{ .reg .u64 t; cvta.to.shared.u64 t, %1; cvt.u32.u64 %0, t; }" : "=r"(a) : "l"(p));
    return a;
}
__device__ __forceinline__ void cp_async16(uint32_t s, const void* g) {
    asm volatile("cp.async.cg.shared.global [%0], [%1], 16;" :: "r"(s), "l"(g) : "memory");
}
__device__ __forceinline__ void cp_commit() {
    asm volatile("cp.async.commit_group;" ::: "memory");
}
template <int N>
__device__ __forceinline__ void cp_wait_group() {
    asm volatile("cp.async.wait_group %0;" :: "n"(N) : "memory");
}
// SW128 swizzle for 128-byte rows
__device__ __forceinline__ uint32_t swz(uint32_t off) {
    return off ^ ((off >> 3) & 0x70);
}
__device__ __forceinline__ void mma16816h(float* c, const uint32_t a[4],
                                          uint32_t b0, uint32_t b1) {
    asm volatile(
        "mma.sync.aligned.m16n8k16.row.col.f32.f16.f16.f32 "
        "{%0,%1,%2,%3}, {%4,%5,%6,%7}, {%8,%9}, {%0,%1,%2,%3};"
        : "+f"(c[0]), "+f"(c[1]), "+f"(c[2]), "+f"(c[3])
        : "r"(a[0]), "r"(a[1]), "r"(a[2]), "r"(a[3]), "r"(b0), "r"(b1));
}
__device__ __forceinline__ void ldsm4(uint32_t r[4], uint32_t addr) {
    asm volatile("ldmatrix.sync.aligned.m8n8.x4.shared.b16 {%0,%1,%2,%3}, [%4];"
                 : "=r"(r[0]), "=r"(r[1]), "=r"(r[2]), "=r"(r[3]) : "r"(addr));
}

// load ROWS x 64 fp16 tile (128B rows) into SW128-swizzled smem (256 threads)
template <int ROWS>
__device__ __forceinline__ void ldtile(uint32_t sdst, const char* g, size_t stride, int tid) {
#pragma unroll
    for (int t = 0; t < ROWS / 32; t++) {
        int op = tid + t * 256;
        int row = op >> 3, c = op & 7;
        uint32_t off = row * 128 + c * 16;
        cp_async16(sdst + swz(off), g + (size_t)row * stride + c * 16);
    }
}

// ============================================================================
// single-term fp16 compute for one k64 stage; warp tile 64x32 (4 mt x 4 nt)
// R9 form (simple serial ldsm->mma chain; proven fastest at 2 CTAs/SM).
// ============================================================================
__device__ __forceinline__ void compute_stage(uint32_t sA, uint32_t sB,
                                              const uint32_t baseA[4],
                                              const uint32_t baseB[2],
                                              float acc[4][4][4]) {
#pragma unroll
    for (int kk = 0; kk < 4; kk++) {
        uint32_t kb = kk * 32;
        uint32_t ah[4][4], bf[2][4];
#pragma unroll
        for (int mt = 0; mt < 4; mt++)
            ldsm4(ah[mt], sA + (baseA[mt] ^ kb));
#pragma unroll
        for (int np = 0; np < 2; np++)
            ldsm4(bf[np], sB + (baseB[np] ^ kb));
#pragma unroll
        for (int np = 0; np < 2; np++) {
#pragma unroll
            for (int h = 0; h < 2; h++) {
                uint32_t b0 = bf[np][h], b1 = bf[np][2 + h];
                int nt = np * 2 + h;
#pragma unroll
                for (int mt = 0; mt < 4; mt++)
                    mma16816h(acc[mt][nt], ah[mt], b0, b1);
            }
        }
    }
}

// ============================================================================
// scores: S[ob][i][j] = sum_n Qt[ob][i][n] * Kt[kvb][jc][n]   (x 2^16)
// CTA tile 128(i) x 128(j), grid (32, 4, 16), block 256, 2 CTAs/SM
// ============================================================================
__global__ void __launch_bounds__(256, 2) scores_mma() {
    extern __shared__ char dsm[];
    uint32_t sb = smem_u32(dsm);
    __shared__ double sred[8], sred2[8];

    int ob = blockIdx.z;
    int kvbase = (ob < 8) ? 8 : 0;
    int i0 = blockIdx.y << 7;
    int j0 = blockIdx.x << 7;
    int kvb = kvbase + (j0 >> 9);
    int jc0 = j0 & 511;

    int tid = threadIdx.x;
    int wid = tid >> 5, lane = tid & 31;
    int g = lane >> 2, tg = lane & 3;
    int wm = (wid & 1) * 64, wn = (wid >> 1) * 32;

    uint32_t baseA[4], baseB[2];
    uint32_t lrow = lane & 15, lcol = (lane >> 4) * 16;
#pragma unroll
    for (int mt = 0; mt < 4; mt++) baseA[mt] = swz((wm + mt * 16 + lrow) * 128 + lcol);
#pragma unroll
    for (int np = 0; np < 2; np++) baseB[np] = swz((wn + np * 16 + lrow) * 128 + lcol);

    const char* AB = (const char*)g_Qt + ((size_t)ob * CH + i0) * NSEQ * 2;
    const char* BB = (const char*)g_Kt + ((size_t)kvb * CH + jc0) * NSEQ * 2;
    const size_t st = NSEQ * 2;

    float acc[4][4][4];
#pragma unroll
    for (int a = 0; a < 4; a++)
#pragma unroll
        for (int b = 0; b < 4; b++)
#pragma unroll
            for (int c = 0; c < 4; c++) acc[a][b][c] = 0.f;

    const int NCH = NSEQ / 64;   // 32

    auto load_chunk = [&](int c, int stg) {
        uint32_t s = sb + stg * STAGE_BYTES;
        size_t ko = (size_t)c * 128;
        ldtile<128>(s,         AB + ko, st, tid);
        ldtile<128>(s + 16384, BB + ko, st, tid);
        cp_commit();
    };

    load_chunk(0, 0);
    load_chunk(1, 1);
    for (int c = 0; c < NCH; c++) {
        if (c + 1 < NCH) cp_wait_group<1>(); else cp_wait_group<0>();
        __syncthreads();
        if (c + 2 < NCH) load_chunk(c + 2, (c + 2) % NSTG);
        uint32_t s = sb + (c % NSTG) * STAGE_BYTES;
        compute_stage(s, s + 16384, baseA, baseB, acc);
    }

    // write scores directly from fragments + fused sum/sumsq
    float* gout = g_S + (size_t)ob * CH * JD;
    float s1 = 0.f, s2 = 0.f;
#pragma unroll
    for (int mt = 0; mt < 4; mt++) {
#pragma unroll
        for (int nt = 0; nt < 4; nt++) {
            int row = i0 + wm + mt * 16 + g;
            int col = j0 + wn + nt * 8 + tg * 2;
            float v0 = acc[mt][nt][0], v1 = acc[mt][nt][1];
            float v2 = acc[mt][nt][2], v3 = acc[mt][nt][3];
            *(float2*)&gout[(size_t)row * JD + col] = make_float2(v0, v1);
            *(float2*)&gout[(size_t)(row + 8) * JD + col] = make_float2(v2, v3);
            s1 += v0 + v1 + v2 + v3;
            s2 += v0 * v0 + v1 * v1 + v2 * v2 + v3 * v3;
        }
    }
    double d1 = (double)s1, d2 = (double)s2;
    for (int off = 16; off > 0; off >>= 1) {
        d1 += __shfl_down_sync(0xffffffffu, d1, off);
        d2 += __shfl_down_sync(0xffffffffu, d2, off);
    }
    if (lane == 0) { sred[wid] = d1; sred2[wid] = d2; }
    __syncthreads();
    if (tid == 0) {
        double t1 = 0.0, t2 = 0.0;
#pragma unroll
        for (int w = 0; w < 8; w++) { t1 += sred[w]; t2 += sred2[w]; }
        atomicAdd(&g_red[2 * ob], t1);
        atomicAdd(&g_red[2 * ob + 1], t2);
    }
}

// ============================================================================
// ctx: CTX[ob][n][i] = sum_j V[kvb(j)][n][jc] * attn[ob][i][j]
// CTA tile 128(n) x 128(i), grid (4, 16, 16), block 256, 2 CTAs/SM
// Direct-fragment fp16 epilogue (half2 stores, true scale).
// ============================================================================
__global__ void __launch_bounds__(256, 2) ctx_mma() {
    extern __shared__ char dsm[];
    uint32_t sb = smem_u32(dsm);

    int ob = blockIdx.z;
    int kvbase = (ob < 8) ? 8 : 0;
    int i0 = blockIdx.x << 7;
    int n0 = blockIdx.y << 7;

    int tid = threadIdx.x;
    int wid = tid >> 5, lane = tid & 31;
    int g = lane >> 2, tg = lane & 3;
    int wm = (wid & 1) * 64, wn = (wid >> 1) * 32;

    uint32_t baseA[4], baseB[2];
    uint32_t lrow = lane & 15, lcol = (lane >> 4) * 16;
#pragma unroll
    for (int mt = 0; mt < 4; mt++) baseA[mt] = swz((wm + mt * 16 + lrow) * 128 + lcol);
#pragma unroll
    for (int np = 0; np < 2; np++) baseB[np] = swz((wn + np * 16 + lrow) * 128 + lcol);

    const char* BB = (const char*)g_A + ((size_t)ob * CH + i0) * JD * 2;

    float acc[4][4][4];
#pragma unroll
    for (int a = 0; a < 4; a++)
#pragma unroll
        for (int b = 0; b < 4; b++)
#pragma unroll
            for (int c = 0; c < 4; c++) acc[a][b][c] = 0.f;

    const int NCH = JD / 64;   // 64

    auto load_chunk = [&](int c, int stg) {
        uint32_t s = sb + stg * STAGE_BYTES;
        int j0c = c * 64;
        int kvb = kvbase + (j0c >> 9);
        int jc0 = j0c & 511;
        const char* Ap = (const char*)g_V + (((size_t)kvb * NSEQ + n0) * CH + jc0) * 2;
        ldtile<128>(s,         Ap, CH * 2, tid);
        ldtile<128>(s + 16384, BB + (size_t)j0c * 2, JD * 2, tid);
        cp_commit();
    };

    load_chunk(0, 0);
    load_chunk(1, 1);
    for (int c = 0; c < NCH; c++) {
        if (c + 1 < NCH) cp_wait_group<1>(); else cp_wait_group<0>();
        __syncthreads();
        if (c + 2 < NCH) load_chunk(c + 2, (c + 2) % NSTG);
        uint32_t s = sb + (c % NSTG) * STAGE_BYTES;
        compute_stage(s, s + 16384, baseA, baseB, acc);
    }

    const float ds = 1.0f / SCALE_F;   // undo V pre-scale
    __half* gout = g_CTXh + (size_t)ob * NSEQ * CH;
#pragma unroll
    for (int mt = 0; mt < 4; mt++) {
#pragma unroll
        for (int nt = 0; nt < 4; nt++) {
            int row = n0 + wm + mt * 16 + g;
            int col = i0 + wn + nt * 8 + tg * 2;
            *(__half2*)&gout[(size_t)row * CH + col] =
                __floats2half2_rn(acc[mt][nt][0] * ds, acc[mt][nt][1] * ds);
            *(__half2*)&gout[(size_t)(row + 8) * CH + col] =
                __floats2half2_rn(acc[mt][nt][2] * ds, acc[mt][nt][3] * ds);
        }
    }
}

// ============================================================================
// fused QKV projection: 128x64 tile, 8x4 per thread x 3 outputs.
// grid (CH/64=8, ROWS_TOT/128=256), 256 threads. Also zeroes g_red.
// ============================================================================
__global__ void __launch_bounds__(256) qkv_gemm(const float* __restrict__ A,
                                                const float* __restrict__ BmQ,
                                                const float* __restrict__ BmK,
                                                const float* __restrict__ BmV,
                                                __half* __restrict__ Qt,
                                                __half* __restrict__ Kt,
                                                __half* __restrict__ Vv) {
    __shared__ __align__(16) float As[16][132];
    __shared__ __align__(16) float BsQ[16][64], BsK[16][64], BsV[16][64];
    const int K = CDIM, N = CH;
    int bm = blockIdx.y * 128, bn = blockIdx.x * 64;
    int tid = threadIdx.x;

    if (blockIdx.x == 0 && blockIdx.y == 0 && tid < BTOT * 2)
        g_red[tid] = 0.0;

    int tx = tid & 15, ty = tid >> 4;
    int br = tid >> 4, bc = (tid & 15) << 2;

    float aq[8][4], akk[8][4], av_[8][4];
#pragma unroll
    for (int i = 0; i < 8; i++)
#pragma unroll
        for (int j = 0; j < 4; j++) { aq[i][j] = 0.f; akk[i][j] = 0.f; av_[i][j] = 0.f; }

    for (int k0 = 0; k0 < K; k0 += 16) {
#pragma unroll
        for (int t = 0; t < 2; t++) {
            int op = tid + t * 256;
            int row = op >> 2, c = (op & 3) * 4;
            float4 v = *(const float4*)&A[(size_t)(bm + row) * K + k0 + c];
            As[c + 0][row] = v.x; As[c + 1][row] = v.y;
            As[c + 2][row] = v.z; As[c + 3][row] = v.w;
        }
        size_t boff = (size_t)(k0 + br) * N + bn + bc;
        *(float4*)&BsQ[br][bc] = *(const float4*)&BmQ[boff];
        *(float4*)&BsK[br][bc] = *(const float4*)&BmK[boff];
        *(float4*)&BsV[br][bc] = *(const float4*)&BmV[boff];
        __syncthreads();
#pragma unroll
        for (int kk = 0; kk < 16; kk++) {
            float a[8];
            *(float4*)&a[0] = *(float4*)&As[kk][ty * 8];
            *(float4*)&a[4] = *(float4*)&As[kk][ty * 8 + 4];
            float bq[4], bk[4], bv[4];
            *(float4*)&bq[0] = *(float4*)&BsQ[kk][tx * 4];
            *(float4*)&bk[0] = *(float4*)&BsK[kk][tx * 4];
            *(float4*)&bv[0] = *(float4*)&BsV[kk][tx * 4];
#pragma unroll
            for (int i = 0; i < 8; i++)
#pragma unroll
                for (int j = 0; j < 4; j++) {
                    aq[i][j]  += a[i] * bq[j];
                    akk[i][j] += a[i] * bk[j];
                    av_[i][j] += a[i] * bv[j];
                }
        }
        __syncthreads();
    }

    {
        int b = bm >> 11;
        int nloc = (bm & 2047) + ty * 8;
#pragma unroll
        for (int j = 0; j < 4; j++) {
            int col = bn + tx * 4 + j;
            union { __half v[8]; uint4 u; } pq, pk;
#pragma unroll
            for (int i = 0; i < 8; i++) {
                pq.v[i] = __float2half(aq[i][j] * SCALE_F);
                pk.v[i] = __float2half(akk[i][j] * SCALE_F);
            }
            size_t off = (size_t)b * (CH * NSEQ) + (size_t)col * NSEQ + nloc;
            *(uint4*)&Qt[off] = pq.u;
            *(uint4*)&Kt[off] = pk.u;
        }
    }
#pragma unroll
    for (int i = 0; i < 8; i++) {
        int m = bm + ty * 8 + i;
        union { __half v[4]; uint2 u; } pv;
#pragma unroll
        for (int j = 0; j < 4; j++)
            pv.v[j] = __float2half(av_[i][j] * SCALE_F);
        *(uint2*)&Vv[(size_t)m * CH + bn + tx * 4] = pv.u;
    }
}

// ============================================================================
// Wo prep: Wo[512][64] fp32 -> g_Wot[64][512] fp16 (K-major rows)
// ============================================================================
__global__ void __launch_bounds__(256) wot_prep(const float* __restrict__ Wo) {
    int idx = blockIdx.x * 256 + threadIdx.x;   // 0..32767
    int k = idx >> 6, n = idx & 63;
    g_Wot[n * CH + k] = __float2half(Wo[(size_t)k * CDIM + n]);
}

// ============================================================================
// out projection via tensor cores: OUT[M,64] = CTXh[M,512] @ Wot^T
// CTA tile 128(m) x 64(c), warp 32x32 (2 mt x 4 nt), grid 256, block 256.
// ============================================================================
__global__ void __launch_bounds__(256, 2) gemm_out_mma(float* __restrict__ Cm) {
    extern __shared__ char dsm[];
    uint32_t sb = smem_u32(dsm);

    int bm = blockIdx.x << 7;
    int tid = threadIdx.x;
    int wid = tid >> 5, lane = tid & 31;
    int g = lane >> 2, tg = lane & 3;
    int wm = (wid & 3) * 32, wn = (wid >> 2) * 32;

    uint32_t baseA[2], baseB[2];
    uint32_t lrow = lane & 15, lcol = (lane >> 4) * 16;
#pragma unroll
    for (int mt = 0; mt < 2; mt++) baseA[mt] = swz((wm + mt * 16 + lrow) * 128 + lcol);
#pragma unroll
    for (int np = 0; np < 2; np++) baseB[np] = swz((wn + np * 16 + lrow) * 128 + lcol);

    const char* AB = (const char*)g_CTXh + (size_t)bm * CH * 2;
    const char* BB = (const char*)g_Wot;

    float acc[2][4][4];
#pragma unroll
    for (int a = 0; a < 2; a++)
#pragma unroll
        for (int b = 0; b < 4; b++)
#pragma unroll
            for (int c = 0; c < 4; c++) acc[a][b][c] = 0.f;

    const int NCH = CH / 64;   // 8

    auto load_chunk = [&](int c, int stg) {
        uint32_t s = sb + stg * OSTAGE_BYTES;
        size_t ko = (size_t)c * 128;
        ldtile<128>(s,         AB + ko, CH * 2, tid);
        ldtile<64>(s + 16384,  BB + ko, CH * 2, tid);
        cp_commit();
    };

    load_chunk(0, 0);
    load_chunk(1, 1);
    for (int c = 0; c < NCH; c++) {
        if (c + 1 < NCH) cp_wait_group<1>(); else cp_wait_group<0>();
        __syncthreads();
        if (c + 2 < NCH) load_chunk(c + 2, (c + 2) % NSTG);
        uint32_t s = sb + (c % NSTG) * OSTAGE_BYTES;
        uint32_t sA = s, sB = s + 16384;
#pragma unroll
        for (int kk = 0; kk < 4; kk++) {
            uint32_t kb = kk * 32;
            uint32_t ah[2][4], bf[2][4];
#pragma unroll
            for (int mt = 0; mt < 2; mt++)
                ldsm4(ah[mt], sA + (baseA[mt] ^ kb));
#pragma unroll
            for (int np = 0; np < 2; np++)
                ldsm4(bf[np], sB + (baseB[np] ^ kb));
#pragma unroll
            for (int np = 0; np < 2; np++) {
#pragma unroll
                for (int h = 0; h < 2; h++) {
                    uint32_t b0 = bf[np][h], b1 = bf[np][2 + h];
                    int nt = np * 2 + h;
#pragma unroll
                    for (int mt = 0; mt < 2; mt++)
                        mma16816h(acc[mt][nt], ah[mt], b0, b1);
                }
            }
        }
        __syncthreads();
    }

#pragma unroll
    for (int mt = 0; mt < 2; mt++) {
#pragma unroll
        for (int nt = 0; nt < 4; nt++) {
            int row = bm + wm + mt * 16 + g;
            int col = wn + nt * 8 + tg * 2;
            *(float2*)&Cm[(size_t)row * CDIM + col] =
                make_float2(acc[mt][nt][0], acc[mt][nt][1]);
            *(float2*)&Cm[(size_t)(row + 8) * CDIM + col] =
                make_float2(acc[mt][nt][2], acc[mt][nt][3]);
        }
    }
}

// ============================================================================
// softmax (fused rstd finalize): scale + softmax over j, write attn fp16.
// ============================================================================
__global__ void __launch_bounds__(256) softmax_k() {
    int row = blockIdx.x;
    int b = row >> 9;
    __shared__ float srstd;
    __shared__ float red[8];
    int t = threadIdx.x;

    if (t == 0) {
        const double SC = 65536.0;   // scores are scaled by 2^16
        double n = (double)CH * (double)JD;
        double mean = g_red[2 * b] / (n * SC);
        double var  = g_red[2 * b + 1] / (n * SC * SC) - mean * mean;
        srstd = rsqrtf((float)var + EPS_F) / (float)SC;
    }

    const float* p = g_S + (size_t)row * JD;
    float4 xv[4];
#pragma unroll
    for (int u = 0; u < 4; u++)
        xv[u] = *(const float4*)&p[u * 1024 + t * 4];
    __syncthreads();
    float rstd = srstd;

    float* x = (float*)xv;
    float mx = -1e30f;
#pragma unroll
    for (int u = 0; u < 16; u++) {
        x[u] *= rstd;
        mx = fmaxf(mx, x[u]);
    }
    for (int off = 16; off > 0; off >>= 1)
        mx = fmaxf(mx, __shfl_xor_sync(0xffffffffu, mx, off));
    int lane = t & 31, wid = t >> 5;
    if (lane == 0) red[wid] = mx;
    __syncthreads();
    float gm = red[0];
#pragma unroll
    for (int w = 1; w < 8; w++) gm = fmaxf(gm, red[w]);
    __syncthreads();

    float sum = 0.f;
#pragma unroll
    for (int u = 0; u < 16; u++) {
        x[u] = __expf(x[u] - gm);
        sum += x[u];
    }
    for (int off = 16; off > 0; off >>= 1)
        sum += __shfl_xor_sync(0xffffffffu, sum, off);
    if (lane == 0) red[wid] = sum;
    __syncthreads();
    float tot = 0.f;
#pragma unroll
    for (int w = 0; w < 8; w++) tot += red[w];
    float inv = 1.0f / tot;

    __half* ah = g_A + (size_t)row * JD;
#pragma unroll
    for (int u = 0; u < 4; u++) {
        union { __half v[4]; uint2 q; } pk;
#pragma unroll
        for (int e = 0; e < 4; e++)
            pk.v[e] = __float2half(x[u * 4 + e] * inv);
        *(uint2*)&ah[u * 1024 + t * 4] = pk.q;
    }
}

// ============================================================================
// launch
// ============================================================================
extern "C" void kernel_launch(void* const* d_in, const int* in_sizes, int n_in,
                              void* d_out, int out_size) {
    const float* emb = (const float*)d_in[0];
    const float* Wq  = (const float*)d_in[1];
    const float* Wk  = (const float*)d_in[2];
    const float* Wv  = (const float*)d_in[3];
    const float* Wo  = (const float*)d_in[4];
    float* outp = (float*)d_out;

    void *qt, *kt, *vv;
    cudaGetSymbolAddress(&qt, g_Qt);
    cudaGetSymbolAddress(&kt, g_Kt);
    cudaGetSymbolAddress(&vv, g_V);

    cudaFuncSetAttribute(scores_mma, cudaFuncAttributeMaxDynamicSharedMemorySize, SMEM_DYN);
    cudaFuncSetAttribute(ctx_mma, cudaFuncAttributeMaxDynamicSharedMemorySize, SMEM_DYN);
    cudaFuncSetAttribute(gemm_out_mma, cudaFuncAttributeMaxDynamicSharedMemorySize, OSMEM_DYN);

    wot_prep<<<128, 256>>>(Wo);
    qkv_gemm<<<dim3(CH / 64, ROWS_TOT / 128), 256>>>(emb, Wq, Wk, Wv,
                                                     (__half*)qt, (__half*)kt, (__half*)vv);

    scores_mma<<<dim3(JD / 128, CH / 128, BTOT), 256, SMEM_DYN>>>();

    softmax_k<<<BTOT * CH, 256>>>();

    ctx_mma<<<dim3(CH / 128, NSEQ / 128, BTOT), 256, SMEM_DYN>>>();

    gemm_out_mma<<<ROWS_TOT / 128, 256, OSMEM_DYN>>>(outp);
}

// round 14
// speedup vs baseline: 1.2385x; 1.1370x over previous
#include <cuda_runtime.h>
#include <cuda_fp16.h>
#include <cstdint>
#include <cstddef>

#define NSEQ  2048
#define CDIM  64
#define CH    512
#define JD    4096
#define BTOT  16
#define ROWS_TOT (BTOT * NSEQ)
#define EPS_F 1e-5f
#define SCALE_F 256.0f          // operand pre-scale (2^8)

// stage (k64): A 128x64 fp16 = 16KB, B 128x64 fp16 = 16KB
#define STAGE_BYTES 32768
#define NSTG 3
#define SMEM_DYN (NSTG * STAGE_BYTES)

// gemm_out stage: A 128x64 fp16 = 16KB, B 64x64 fp16 = 8KB
#define OSTAGE_BYTES 24576
#define OSMEM_DYN (NSTG * OSTAGE_BYTES)

// qkv smem: emb 128x64 (16KB) + 6 W tiles 64x64 (8KB each) = 64KB
#define QSMEM 65536

// ---------------- scratch ----------------
__device__ __half g_embh[(size_t)ROWS_TOT * CDIM];  // emb fp16
__device__ __half g_Ws[(size_t)6 * CH * CDIM];      // Wq h/l, Wk h/l, Wv h/l (x256), [n][k]
__device__ __half g_Qt[(size_t)BTOT * CH * NSEQ];   // [b][i][n], x256
__device__ __half g_Kt[(size_t)BTOT * CH * NSEQ];   // [b][j][n], x256
__device__ __half g_V [(size_t)BTOT * NSEQ * CH];   // [b][n][c], x256
__device__ float  g_S [(size_t)BTOT * CH * JD];     // scores, x2^16
__device__ __half g_A [(size_t)BTOT * CH * JD];     // attn fp16 [b][i][j]
__device__ __half g_CTXh[(size_t)BTOT * NSEQ * CH]; // ctx fp16, true scale
__device__ __half g_Wot[CDIM * CH];                 // Wo^T fp16 [c][k]
__device__ double g_red[BTOT * 2];

// ---------------- helpers ----------------
__device__ __forceinline__ uint32_t smem_u32(const void* p) {
    uint32_t a;
    asm("{ .reg .u64 t; cvta.to.shared.u64 t, %1; cvt.u32.u64 %0, t; }" : "=r"(a) : "l"(p));
    return a;
}
__device__ __forceinline__ void cp_async16(uint32_t s, const void* g) {
    asm volatile("cp.async.cg.shared.global [%0], [%1], 16;" :: "r"(s), "l"(g) : "memory");
}
__device__ __forceinline__ void cp_commit() {
    asm volatile("cp.async.commit_group;" ::: "memory");
}
template <int N>
__device__ __forceinline__ void cp_wait_group() {
    asm volatile("cp.async.wait_group %0;" :: "n"(N) : "memory");
}
// SW128 swizzle for 128-byte rows
__device__ __forceinline__ uint32_t swz(uint32_t off) {
    return off ^ ((off >> 3) & 0x70);
}
__device__ __forceinline__ void mma16816h(float* c, const uint32_t a[4],
                                          uint32_t b0, uint32_t b1) {
    asm volatile(
        "mma.sync.aligned.m16n8k16.row.col.f32.f16.f16.f32 "
        "{%0,%1,%2,%3}, {%4,%5,%6,%7}, {%8,%9}, {%0,%1,%2,%3};"
        : "+f"(c[0]), "+f"(c[1]), "+f"(c[2]), "+f"(c[3])
        : "r"(a[0]), "r"(a[1]), "r"(a[2]), "r"(a[3]), "r"(b0), "r"(b1));
}
__device__ __forceinline__ void ldsm4(uint32_t r[4], uint32_t addr) {
    asm volatile("ldmatrix.sync.aligned.m8n8.x4.shared.b16 {%0,%1,%2,%3}, [%4];"
                 : "=r"(r[0]), "=r"(r[1]), "=r"(r[2]), "=r"(r[3]) : "r"(addr));
}

// load ROWS x 64 fp16 tile (128B rows) into SW128-swizzled smem (256 threads)
template <int ROWS>
__device__ __forceinline__ void ldtile(uint32_t sdst, const char* g, size_t stride, int tid) {
#pragma unroll
    for (int t = 0; t < ROWS / 32; t++) {
        int op = tid + t * 256;
        int row = op >> 3, c = op & 7;
        uint32_t off = row * 128 + c * 16;
        cp_async16(sdst + swz(off), g + (size_t)row * stride + c * 16);
    }
}

// ============================================================================
// single-term fp16 compute for one k64 stage; warp tile 64x32 (4 mt x 4 nt)
// ============================================================================
__device__ __forceinline__ void compute_stage(uint32_t sA, uint32_t sB,
                                              const uint32_t baseA[4],
                                              const uint32_t baseB[2],
                                              float acc[4][4][4]) {
#pragma unroll
    for (int kk = 0; kk < 4; kk++) {
        uint32_t kb = kk * 32;
        uint32_t ah[4][4], bf[2][4];
#pragma unroll
        for (int mt = 0; mt < 4; mt++)
            ldsm4(ah[mt], sA + (baseA[mt] ^ kb));
#pragma unroll
        for (int np = 0; np < 2; np++)
            ldsm4(bf[np], sB + (baseB[np] ^ kb));
#pragma unroll
        for (int np = 0; np < 2; np++) {
#pragma unroll
            for (int h = 0; h < 2; h++) {
                uint32_t b0 = bf[np][h], b1 = bf[np][2 + h];
                int nt = np * 2 + h;
#pragma unroll
                for (int mt = 0; mt < 4; mt++)
                    mma16816h(acc[mt][nt], ah[mt], b0, b1);
            }
        }
    }
}

// ============================================================================
// scores: S[ob][i][j] = sum_n Qt[ob][i][n] * Kt[kvb][jc][n]   (x 2^16)
// CTA tile 128(i) x 128(j), grid (32, 4, 16), block 256, 2 CTAs/SM
// ============================================================================
__global__ void __launch_bounds__(256, 2) scores_mma() {
    extern __shared__ char dsm[];
    uint32_t sb = smem_u32(dsm);
    __shared__ double sred[8], sred2[8];

    int ob = blockIdx.z;
    int kvbase = (ob < 8) ? 8 : 0;
    int i0 = blockIdx.y << 7;
    int j0 = blockIdx.x << 7;
    int kvb = kvbase + (j0 >> 9);
    int jc0 = j0 & 511;

    int tid = threadIdx.x;
    int wid = tid >> 5, lane = tid & 31;
    int g = lane >> 2, tg = lane & 3;
    int wm = (wid & 1) * 64, wn = (wid >> 1) * 32;

    uint32_t baseA[4], baseB[2];
    uint32_t lrow = lane & 15, lcol = (lane >> 4) * 16;
#pragma unroll
    for (int mt = 0; mt < 4; mt++) baseA[mt] = swz((wm + mt * 16 + lrow) * 128 + lcol);
#pragma unroll
    for (int np = 0; np < 2; np++) baseB[np] = swz((wn + np * 16 + lrow) * 128 + lcol);

    const char* AB = (const char*)g_Qt + ((size_t)ob * CH + i0) * NSEQ * 2;
    const char* BB = (const char*)g_Kt + ((size_t)kvb * CH + jc0) * NSEQ * 2;
    const size_t st = NSEQ * 2;

    float acc[4][4][4];
#pragma unroll
    for (int a = 0; a < 4; a++)
#pragma unroll
        for (int b = 0; b < 4; b++)
#pragma unroll
            for (int c = 0; c < 4; c++) acc[a][b][c] = 0.f;

    const int NCH = NSEQ / 64;   // 32

    auto load_chunk = [&](int c, int stg) {
        uint32_t s = sb + stg * STAGE_BYTES;
        size_t ko = (size_t)c * 128;
        ldtile<128>(s,         AB + ko, st, tid);
        ldtile<128>(s + 16384, BB + ko, st, tid);
        cp_commit();
    };

    load_chunk(0, 0);
    load_chunk(1, 1);
    for (int c = 0; c < NCH; c++) {
        if (c + 1 < NCH) cp_wait_group<1>(); else cp_wait_group<0>();
        __syncthreads();
        if (c + 2 < NCH) load_chunk(c + 2, (c + 2) % NSTG);
        uint32_t s = sb + (c % NSTG) * STAGE_BYTES;
        compute_stage(s, s + 16384, baseA, baseB, acc);
    }

    float* gout = g_S + (size_t)ob * CH * JD;
    float s1 = 0.f, s2 = 0.f;
#pragma unroll
    for (int mt = 0; mt < 4; mt++) {
#pragma unroll
        for (int nt = 0; nt < 4; nt++) {
            int row = i0 + wm + mt * 16 + g;
            int col = j0 + wn + nt * 8 + tg * 2;
            float v0 = acc[mt][nt][0], v1 = acc[mt][nt][1];
            float v2 = acc[mt][nt][2], v3 = acc[mt][nt][3];
            *(float2*)&gout[(size_t)row * JD + col] = make_float2(v0, v1);
            *(float2*)&gout[(size_t)(row + 8) * JD + col] = make_float2(v2, v3);
            s1 += v0 + v1 + v2 + v3;
            s2 += v0 * v0 + v1 * v1 + v2 * v2 + v3 * v3;
        }
    }
    double d1 = (double)s1, d2 = (double)s2;
    for (int off = 16; off > 0; off >>= 1) {
        d1 += __shfl_down_sync(0xffffffffu, d1, off);
        d2 += __shfl_down_sync(0xffffffffu, d2, off);
    }
    if (lane == 0) { sred[wid] = d1; sred2[wid] = d2; }
    __syncthreads();
    if (tid == 0) {
        double t1 = 0.0, t2 = 0.0;
#pragma unroll
        for (int w = 0; w < 8; w++) { t1 += sred[w]; t2 += sred2[w]; }
        atomicAdd(&g_red[2 * ob], t1);
        atomicAdd(&g_red[2 * ob + 1], t2);
    }
}

// ============================================================================
// ctx: CTX[ob][n][i] = sum_j V[kvb(j)][n][jc] * attn[ob][i][j]
// CTA tile 128(n) x 128(i), grid (4, 16, 16), block 256, 2 CTAs/SM
// ============================================================================
__global__ void __launch_bounds__(256, 2) ctx_mma() {
    extern __shared__ char dsm[];
    uint32_t sb = smem_u32(dsm);

    int ob = blockIdx.z;
    int kvbase = (ob < 8) ? 8 : 0;
    int i0 = blockIdx.x << 7;
    int n0 = blockIdx.y << 7;

    int tid = threadIdx.x;
    int wid = tid >> 5, lane = tid & 31;
    int g = lane >> 2, tg = lane & 3;
    int wm = (wid & 1) * 64, wn = (wid >> 1) * 32;

    uint32_t baseA[4], baseB[2];
    uint32_t lrow = lane & 15, lcol = (lane >> 4) * 16;
#pragma unroll
    for (int mt = 0; mt < 4; mt++) baseA[mt] = swz((wm + mt * 16 + lrow) * 128 + lcol);
#pragma unroll
    for (int np = 0; np < 2; np++) baseB[np] = swz((wn + np * 16 + lrow) * 128 + lcol);

    const char* BB = (const char*)g_A + ((size_t)ob * CH + i0) * JD * 2;

    float acc[4][4][4];
#pragma unroll
    for (int a = 0; a < 4; a++)
#pragma unroll
        for (int b = 0; b < 4; b++)
#pragma unroll
            for (int c = 0; c < 4; c++) acc[a][b][c] = 0.f;

    const int NCH = JD / 64;   // 64

    auto load_chunk = [&](int c, int stg) {
        uint32_t s = sb + stg * STAGE_BYTES;
        int j0c = c * 64;
        int kvb = kvbase + (j0c >> 9);
        int jc0 = j0c & 511;
        const char* Ap = (const char*)g_V + (((size_t)kvb * NSEQ + n0) * CH + jc0) * 2;
        ldtile<128>(s,         Ap, CH * 2, tid);
        ldtile<128>(s + 16384, BB + (size_t)j0c * 2, JD * 2, tid);
        cp_commit();
    };

    load_chunk(0, 0);
    load_chunk(1, 1);
    for (int c = 0; c < NCH; c++) {
        if (c + 1 < NCH) cp_wait_group<1>(); else cp_wait_group<0>();
        __syncthreads();
        if (c + 2 < NCH) load_chunk(c + 2, (c + 2) % NSTG);
        uint32_t s = sb + (c % NSTG) * STAGE_BYTES;
        compute_stage(s, s + 16384, baseA, baseB, acc);
    }

    const float ds = 1.0f / SCALE_F;   // undo V pre-scale
    __half* gout = g_CTXh + (size_t)ob * NSEQ * CH;
#pragma unroll
    for (int mt = 0; mt < 4; mt++) {
#pragma unroll
        for (int nt = 0; nt < 4; nt++) {
            int row = n0 + wm + mt * 16 + g;
            int col = i0 + wn + nt * 8 + tg * 2;
            *(__half2*)&gout[(size_t)row * CH + col] =
                __floats2half2_rn(acc[mt][nt][0] * ds, acc[mt][nt][1] * ds);
            *(__half2*)&gout[(size_t)(row + 8) * CH + col] =
                __floats2half2_rn(acc[mt][nt][2] * ds, acc[mt][nt][3] * ds);
        }
    }
}

// ============================================================================
// prep: emb fp32 -> fp16 (and zero g_red)
// ============================================================================
__global__ void __launch_bounds__(256) embh_prep(const float* __restrict__ emb) {
    size_t idx = ((size_t)blockIdx.x * 256 + threadIdx.x) * 4;
    if (blockIdx.x == 0 && threadIdx.x < BTOT * 2) g_red[threadIdx.x] = 0.0;
    float4 v = *(const float4*)&emb[idx];
    union { __half h[4]; uint2 u; } p;
    p.h[0] = __float2half(v.x); p.h[1] = __float2half(v.y);
    p.h[2] = __float2half(v.z); p.h[3] = __float2half(v.w);
    *(uint2*)&g_embh[idx] = p.u;
}

// ============================================================================
// prep: W[64][512] fp32 -> split fp16 x256, K-major [n][k].
// grid (128, 3); y selects Wq/Wk/Wv.
// ============================================================================
__global__ void __launch_bounds__(256) wqkv_prep(const float* __restrict__ Wq,
                                                 const float* __restrict__ Wk,
                                                 const float* __restrict__ Wv) {
    int idx = blockIdx.x * 256 + threadIdx.x;   // 0..32767
    int w = blockIdx.y;
    const float* src = (w == 0) ? Wq : (w == 1) ? Wk : Wv;
    int n = idx >> 6, k = idx & 63;
    float v = src[(size_t)k * CH + n] * SCALE_F;
    __half h = __float2half(v);
    __half l = __float2half(v - __half2float(h));
    size_t base = (size_t)(2 * w) * CH * CDIM;
    g_Ws[base + (size_t)n * CDIM + k] = h;
    g_Ws[base + CH * CDIM + (size_t)n * CDIM + k] = l;
}

// ============================================================================
// QKV via tensor cores: Qt/Kt/V = embh @ Wsplit (x256).
// CTA tile 128(m) x 64(n), 8 warps 32x32, grid (CH/64=8, ROWS_TOT/128=256).
// Single k64 stage (K=CDIM=64). Qt/Kt transposed via smem stage; V direct.
// ============================================================================
__global__ void __launch_bounds__(256) qkv_mma() {
    extern __shared__ char dsm[];
    uint32_t sb = smem_u32(dsm);
    uint32_t sEmb = sb;

    int bn = blockIdx.x << 6;
    int bm = blockIdx.y << 7;
    int tid = threadIdx.x;
    int wid = tid >> 5, lane = tid & 31;
    int g = lane >> 2, tg = lane & 3;
    int wm = (wid & 3) * 32, wn = (wid >> 2) * 32;

    uint32_t baseA[2], baseB[2];
    uint32_t lrow = lane & 15, lcol = (lane >> 4) * 16;
#pragma unroll
    for (int mt = 0; mt < 2; mt++) baseA[mt] = swz((wm + mt * 16 + lrow) * 128 + lcol);
#pragma unroll
    for (int np = 0; np < 2; np++) baseB[np] = swz((wn + np * 16 + lrow) * 128 + lcol);

    // loads
    ldtile<128>(sEmb, (const char*)g_embh + (size_t)bm * CDIM * 2, CDIM * 2, tid);
#pragma unroll
    for (int w6 = 0; w6 < 6; w6++) {
        const char* wp = (const char*)g_Ws + ((size_t)w6 * CH + bn) * CDIM * 2;
        ldtile<64>(sb + 16384 + w6 * 8192, wp, CDIM * 2, tid);
    }
    cp_commit();
    cp_wait_group<0>();
    __syncthreads();

    float acc[3][2][4][4];
#pragma unroll
    for (int w = 0; w < 3; w++)
#pragma unroll
        for (int a = 0; a < 2; a++)
#pragma unroll
            for (int b = 0; b < 4; b++)
#pragma unroll
                for (int c = 0; c < 4; c++) acc[w][a][b][c] = 0.f;

#pragma unroll
    for (int kk = 0; kk < 4; kk++) {
        uint32_t kb = kk * 32;
        uint32_t ah[2][4];
#pragma unroll
        for (int mt = 0; mt < 2; mt++)
            ldsm4(ah[mt], sEmb + (baseA[mt] ^ kb));
#pragma unroll
        for (int w = 0; w < 3; w++) {
            uint32_t sH = sb + 16384 + (2 * w) * 8192;
            uint32_t sL = sH + 8192;
            uint32_t bh[2][4], bl[2][4];
#pragma unroll
            for (int np = 0; np < 2; np++) {
                ldsm4(bh[np], sH + (baseB[np] ^ kb));
                ldsm4(bl[np], sL + (baseB[np] ^ kb));
            }
#pragma unroll
            for (int np = 0; np < 2; np++) {
#pragma unroll
                for (int h = 0; h < 2; h++) {
                    int nt = np * 2 + h;
#pragma unroll
                    for (int mt = 0; mt < 2; mt++) {
                        mma16816h(acc[w][mt][nt], ah[mt], bh[np][h], bh[np][2 + h]);
                        mma16816h(acc[w][mt][nt], ah[mt], bl[np][h], bl[np][2 + h]);
                    }
                }
            }
        }
    }

    // V direct (row-major [m][c])
#pragma unroll
    for (int mt = 0; mt < 2; mt++) {
#pragma unroll
        for (int nt = 0; nt < 4; nt++) {
            int row = bm + wm + mt * 16 + g;
            int col = bn + wn + nt * 8 + tg * 2;
            *(__half2*)&g_V[(size_t)row * CH + col] =
                __floats2half2_rn(acc[2][mt][nt][0], acc[2][mt][nt][1]);
            *(__half2*)&g_V[(size_t)(row + 8) * CH + col] =
                __floats2half2_rn(acc[2][mt][nt][2], acc[2][mt][nt][3]);
        }
    }

    // Qt / Kt transposed via smem stage (pitch 136 halves)
    __half* stT = (__half*)dsm;
    int b = bm >> 11;
    int nloc = bm & 2047;
#pragma unroll
    for (int w = 0; w < 2; w++) {
        __syncthreads();
#pragma unroll
        for (int mt = 0; mt < 2; mt++) {
#pragma unroll
            for (int nt = 0; nt < 4; nt++) {
                int m = wm + mt * 16 + g;
                int col = wn + nt * 8 + tg * 2;
                stT[(col + 0) * 136 + m]     = __float2half(acc[w][mt][nt][0]);
                stT[(col + 1) * 136 + m]     = __float2half(acc[w][mt][nt][1]);
                stT[(col + 0) * 136 + m + 8] = __float2half(acc[w][mt][nt][2]);
                stT[(col + 1) * 136 + m + 8] = __float2half(acc[w][mt][nt][3]);
            }
        }
        __syncthreads();
        __half* dst = ((w == 0) ? g_Qt : g_Kt) +
                      (size_t)b * CH * NSEQ + (size_t)bn * NSEQ + nloc;
#pragma unroll
        for (int k = 0; k < 4; k++) {
            int idx = tid + k * 256;
            int row = idx >> 4, c8 = (idx & 15) * 8;
            *(uint4*)&dst[(size_t)row * NSEQ + c8] = *(uint4*)&stT[row * 136 + c8];
        }
    }
}

// ============================================================================
// Wo prep: Wo[512][64] fp32 -> g_Wot[64][512] fp16 (K-major rows)
// ============================================================================
__global__ void __launch_bounds__(256) wot_prep(const float* __restrict__ Wo) {
    int idx = blockIdx.x * 256 + threadIdx.x;   // 0..32767
    int k = idx >> 6, n = idx & 63;
    g_Wot[n * CH + k] = __float2half(Wo[(size_t)k * CDIM + n]);
}

// ============================================================================
// out projection via tensor cores: OUT[M,64] = CTXh[M,512] @ Wot^T
// ============================================================================
__global__ void __launch_bounds__(256, 2) gemm_out_mma(float* __restrict__ Cm) {
    extern __shared__ char dsm[];
    uint32_t sb = smem_u32(dsm);

    int bm = blockIdx.x << 7;
    int tid = threadIdx.x;
    int wid = tid >> 5, lane = tid & 31;
    int g = lane >> 2, tg = lane & 3;
    int wm = (wid & 3) * 32, wn = (wid >> 2) * 32;

    uint32_t baseA[2], baseB[2];
    uint32_t lrow = lane & 15, lcol = (lane >> 4) * 16;
#pragma unroll
    for (int mt = 0; mt < 2; mt++) baseA[mt] = swz((wm + mt * 16 + lrow) * 128 + lcol);
#pragma unroll
    for (int np = 0; np < 2; np++) baseB[np] = swz((wn + np * 16 + lrow) * 128 + lcol);

    const char* AB = (const char*)g_CTXh + (size_t)bm * CH * 2;
    const char* BB = (const char*)g_Wot;

    float acc[2][4][4];
#pragma unroll
    for (int a = 0; a < 2; a++)
#pragma unroll
        for (int b = 0; b < 4; b++)
#pragma unroll
            for (int c = 0; c < 4; c++) acc[a][b][c] = 0.f;

    const int NCH = CH / 64;   // 8

    auto load_chunk = [&](int c, int stg) {
        uint32_t s = sb + stg * OSTAGE_BYTES;
        size_t ko = (size_t)c * 128;
        ldtile<128>(s,         AB + ko, CH * 2, tid);
        ldtile<64>(s + 16384,  BB + ko, CH * 2, tid);
        cp_commit();
    };

    load_chunk(0, 0);
    load_chunk(1, 1);
    for (int c = 0; c < NCH; c++) {
        if (c + 1 < NCH) cp_wait_group<1>(); else cp_wait_group<0>();
        __syncthreads();
        if (c + 2 < NCH) load_chunk(c + 2, (c + 2) % NSTG);
        uint32_t s = sb + (c % NSTG) * OSTAGE_BYTES;
        uint32_t sA = s, sB = s + 16384;
#pragma unroll
        for (int kk = 0; kk < 4; kk++) {
            uint32_t kb = kk * 32;
            uint32_t ah[2][4], bf[2][4];
#pragma unroll
            for (int mt = 0; mt < 2; mt++)
                ldsm4(ah[mt], sA + (baseA[mt] ^ kb));
#pragma unroll
            for (int np = 0; np < 2; np++)
                ldsm4(bf[np], sB + (baseB[np] ^ kb));
#pragma unroll
            for (int np = 0; np < 2; np++) {
#pragma unroll
                for (int h = 0; h < 2; h++) {
                    uint32_t b0 = bf[np][h], b1 = bf[np][2 + h];
                    int nt = np * 2 + h;
#pragma unroll
                    for (int mt = 0; mt < 2; mt++)
                        mma16816h(acc[mt][nt], ah[mt], b0, b1);
                }
            }
        }
        __syncthreads();
    }

#pragma unroll
    for (int mt = 0; mt < 2; mt++) {
#pragma unroll
        for (int nt = 0; nt < 4; nt++) {
            int row = bm + wm + mt * 16 + g;
            int col = wn + nt * 8 + tg * 2;
            *(float2*)&Cm[(size_t)row * CDIM + col] =
                make_float2(acc[mt][nt][0], acc[mt][nt][1]);
            *(float2*)&Cm[(size_t)(row + 8) * CDIM + col] =
                make_float2(acc[mt][nt][2], acc[mt][nt][3]);
        }
    }
}

// ============================================================================
// softmax (fused rstd finalize): scale + softmax over j, write attn fp16.
// ============================================================================
__global__ void __launch_bounds__(256) softmax_k() {
    int row = blockIdx.x;
    int b = row >> 9;
    __shared__ float srstd;
    __shared__ float red[8];
    int t = threadIdx.x;

    if (t == 0) {
        const double SC = 65536.0;   // scores are scaled by 2^16
        double n = (double)CH * (double)JD;
        double mean = g_red[2 * b] / (n * SC);
        double var  = g_red[2 * b + 1] / (n * SC * SC) - mean * mean;
        srstd = rsqrtf((float)var + EPS_F) / (float)SC;
    }

    const float* p = g_S + (size_t)row * JD;
    float4 xv[4];
#pragma unroll
    for (int u = 0; u < 4; u++)
        xv[u] = *(const float4*)&p[u * 1024 + t * 4];
    __syncthreads();
    float rstd = srstd;

    float* x = (float*)xv;
    float mx = -1e30f;
#pragma unroll
    for (int u = 0; u < 16; u++) {
        x[u] *= rstd;
        mx = fmaxf(mx, x[u]);
    }
    for (int off = 16; off > 0; off >>= 1)
        mx = fmaxf(mx, __shfl_xor_sync(0xffffffffu, mx, off));
    int lane = t & 31, wid = t >> 5;
    if (lane == 0) red[wid] = mx;
    __syncthreads();
    float gm = red[0];
#pragma unroll
    for (int w = 1; w < 8; w++) gm = fmaxf(gm, red[w]);
    __syncthreads();

    float sum = 0.f;
#pragma unroll
    for (int u = 0; u < 16; u++) {
        x[u] = __expf(x[u] - gm);
        sum += x[u];
    }
    for (int off = 16; off > 0; off >>= 1)
        sum += __shfl_xor_sync(0xffffffffu, sum, off);
    if (lane == 0) red[wid] = sum;
    __syncthreads();
    float tot = 0.f;
#pragma unroll
    for (int w = 0; w < 8; w++) tot += red[w];
    float inv = 1.0f / tot;

    __half* ah = g_A + (size_t)row * JD;
#pragma unroll
    for (int u = 0; u < 4; u++) {
        union { __half v[4]; uint2 q; } pk;
#pragma unroll
        for (int e = 0; e < 4; e++)
            pk.v[e] = __float2half(x[u * 4 + e] * inv);
        *(uint2*)&ah[u * 1024 + t * 4] = pk.q;
    }
}

// ============================================================================
// launch
// ============================================================================
extern "C" void kernel_launch(void* const* d_in, const int* in_sizes, int n_in,
                              void* d_out, int out_size) {
    const float* emb = (const float*)d_in[0];
    const float* Wq  = (const float*)d_in[1];
    const float* Wk  = (const float*)d_in[2];
    const float* Wv  = (const float*)d_in[3];
    const float* Wo  = (const float*)d_in[4];
    float* outp = (float*)d_out;

    cudaFuncSetAttribute(scores_mma, cudaFuncAttributeMaxDynamicSharedMemorySize, SMEM_DYN);
    cudaFuncSetAttribute(ctx_mma, cudaFuncAttributeMaxDynamicSharedMemorySize, SMEM_DYN);
    cudaFuncSetAttribute(gemm_out_mma, cudaFuncAttributeMaxDynamicSharedMemorySize, OSMEM_DYN);
    cudaFuncSetAttribute(qkv_mma, cudaFuncAttributeMaxDynamicSharedMemorySize, QSMEM);

    embh_prep<<<ROWS_TOT * CDIM / 1024, 256>>>(emb);
    wqkv_prep<<<dim3(128, 3), 256>>>(Wq, Wk, Wv);
    wot_prep<<<128, 256>>>(Wo);

    qkv_mma<<<dim3(CH / 64, ROWS_TOT / 128), 256, QSMEM>>>();

    scores_mma<<<dim3(JD / 128, CH / 128, BTOT), 256, SMEM_DYN>>>();

    softmax_k<<<BTOT * CH, 256>>>();

    ctx_mma<<<dim3(CH / 128, NSEQ / 128, BTOT), 256, SMEM_DYN>>>();

    gemm_out_mma<<<ROWS_TOT / 128, 256, OSMEM_DYN>>>(outp);
}